// round 5
// baseline (speedup 1.0000x reference)
#include <cuda_runtime.h>

#define NN 50000
#define DD 128
#define EE 600000
#define CC 40
#define LL 4

// ---------------- scratch (static device globals; no allocation) ----------------
__device__ float g_h  [NN * DD];
__device__ float g_ht [NN * DD];
__device__ float g_agg[NN * DD];
__device__ float g_gate[NN];
__device__ int   g_rowptr[NN + 1];
__device__ int   g_cursor[NN];
__device__ int   g_srcs[EE + NN];

// ---------------- helpers ----------------
__device__ __forceinline__ unsigned long long ffma2(unsigned long long a,
                                                    unsigned long long b,
                                                    unsigned long long c) {
    unsigned long long d;
    asm("fma.rn.f32x2 %0, %1, %2, %3;" : "=l"(d) : "l"(a), "l"(b), "l"(c));
    return d;
}
__device__ __forceinline__ unsigned long long pack2(float x, float y) {
    unsigned long long r;
    asm("mov.b64 %0, {%1, %2};" : "=l"(r) : "f"(x), "f"(y));
    return r;
}
__device__ __forceinline__ float2 unpack2(unsigned long long v) {
    float2 f;
    asm("mov.b64 {%0, %1}, %2;" : "=f"(f.x), "=f"(f.y) : "l"(v));
    return f;
}
__device__ __forceinline__ float hsw(float x) {
    return x * fminf(fmaxf(x + 3.f, 0.f), 6.f) * (1.f / 6.f);
}

// ---------------- CSR build ----------------
__global__ void init_deg_kernel(int* __restrict__ cursor, int n) {
    int i = blockIdx.x * blockDim.x + threadIdx.x;
    if (i < n) cursor[i] = 1;  // self loop
}

__global__ void count_kernel(const int* __restrict__ dst, int* __restrict__ cursor, int e) {
    int i = blockIdx.x * blockDim.x + threadIdx.x;
    if (i < e) atomicAdd(&cursor[dst[i]], 1);
}

__global__ void scan_kernel(int* __restrict__ cursor, int* __restrict__ rowptr, int n) {
    __shared__ int wsum[32];
    const int lane = threadIdx.x & 31;
    const int wid  = threadIdx.x >> 5;
    int carry = 0;
    for (int base = 0; base < n; base += 1024) {
        int i = base + threadIdx.x;
        int v = (i < n) ? cursor[i] : 0;
        int x = v;
        #pragma unroll
        for (int o = 1; o < 32; o <<= 1) {
            int y = __shfl_up_sync(0xffffffffu, x, o);
            if (lane >= o) x += y;
        }
        if (lane == 31) wsum[wid] = x;
        __syncthreads();
        if (wid == 0) {
            int s = wsum[lane];
            #pragma unroll
            for (int o = 1; o < 32; o <<= 1) {
                int y = __shfl_up_sync(0xffffffffu, s, o);
                if (lane >= o) s += y;
            }
            wsum[lane] = s;
        }
        __syncthreads();
        int off  = carry + (wid ? wsum[wid - 1] : 0);
        int excl = off + x - v;
        if (i < n) { rowptr[i] = excl; cursor[i] = excl; }
        carry += wsum[31];
        __syncthreads();
    }
    if (threadIdx.x == 0) rowptr[n] = carry;
}

__global__ void scatter_kernel(const int* __restrict__ src, const int* __restrict__ dst,
                               int* __restrict__ cursor, int* __restrict__ srcs,
                               int e, int n) {
    int i = blockIdx.x * blockDim.x + threadIdx.x;
    if (i >= e + n) return;
    int d, s;
    if (i < e) { d = dst[i]; s = src[i]; }
    else       { d = i - e;  s = i - e;  }
    int p = atomicAdd(&cursor[d], 1);
    srcs[p] = s;
}

// ---------------- per-node gate logits: g = h . Wg + bg ----------------
__global__ void gate_kernel(const float* __restrict__ h, const float* __restrict__ Wg,
                            const float* __restrict__ bg, float* __restrict__ g, int n) {
    int gt   = blockIdx.x * blockDim.x + threadIdx.x;
    int w    = gt >> 5;
    int lane = gt & 31;
    if (w >= n) return;
    float4 a = ((const float4*)(h + (size_t)w * DD))[lane];
    float4 b = ((const float4*)Wg)[lane];
    float s  = a.x * b.x + a.y * b.y + a.z * b.z + a.w * b.w;
    #pragma unroll
    for (int o = 16; o; o >>= 1) s += __shfl_xor_sync(0xffffffffu, s, o);
    if (lane == 0) g[w] = s + bg[0];
}

// ---------------- fused softmax-attention aggregation (warp per dst node) -----
__global__ void edge_agg_kernel(const int* __restrict__ rowptr, const int* __restrict__ srcs,
                                const float* __restrict__ g, const float* __restrict__ ht,
                                float* __restrict__ agg, int n) {
    int gt   = blockIdx.x * blockDim.x + threadIdx.x;
    int w    = gt >> 5;
    int lane = gt & 31;
    if (w >= n) return;
    int beg = rowptr[w];
    int end = rowptr[w + 1];

    float m = -3.4e38f;
    for (int j = beg + lane; j < end; j += 32) m = fmaxf(m, g[srcs[j]]);
    #pragma unroll
    for (int o = 16; o; o >>= 1) m = fmaxf(m, __shfl_xor_sync(0xffffffffu, m, o));

    float s = 0.f;
    for (int j = beg + lane; j < end; j += 32) s += __expf(g[srcs[j]] - m);
    #pragma unroll
    for (int o = 16; o; o >>= 1) s += __shfl_xor_sync(0xffffffffu, s, o);
    float inv = 1.f / s;

    float4 acc = make_float4(0.f, 0.f, 0.f, 0.f);
    for (int j = beg; j < end; j++) {
        int   sj  = srcs[j];                      // broadcast load across warp
        float wgt = __expf(g[sj] - m) * inv;      // redundant per lane (cheap MUFU)
        float4 v  = ((const float4*)(ht + (size_t)sj * DD))[lane];
        acc.x = fmaf(wgt, v.x, acc.x);
        acc.y = fmaf(wgt, v.y, acc.y);
        acc.z = fmaf(wgt, v.z, acc.z);
        acc.w = fmaf(wgt, v.w, acc.w);
    }
    ((float4*)(agg + (size_t)w * DD))[lane] = acc;
}

// ---------------- SGEMM (N x 128) @ (128 x 128) with fused epilogue ----------
// EPI 0: +bias    EPI 1: +bias, BN(eval), hardswish    EPI 2: +bias, hardswish
// Block: 256 threads, tile 64 rows x 128 cols, f32x2 packed FMA.
template <int EPI>
__global__ void __launch_bounds__(256, 2)
gemm128(const float* __restrict__ A, const float* __restrict__ W,
        const float* __restrict__ bias,
        const float* __restrict__ bng, const float* __restrict__ bnb,
        const float* __restrict__ bnm, const float* __restrict__ bnv,
        float* __restrict__ out, int nrows) {
    extern __shared__ float sm[];
    float* Ws = sm;             // 128*128 floats
    float* As = sm + DD * DD;   // 64*128 floats
    const int tid  = threadIdx.x;
    const int row0 = blockIdx.x * 64;

    {   // stage W (coalesced float4)
        const float4* Wg4 = (const float4*)W;
        float4* Ws4 = (float4*)Ws;
        #pragma unroll
        for (int it = 0; it < 16; it++) Ws4[it * 256 + tid] = Wg4[it * 256 + tid];
    }
    {   // stage A tile (coalesced float4, zero-fill OOB rows)
        float4* As4 = (float4*)As;
        #pragma unroll
        for (int it = 0; it < 8; it++) {
            int idx = it * 256 + tid;        // 0..2047
            int r   = idx >> 5;
            int c4  = idx & 31;
            float4 v = make_float4(0.f, 0.f, 0.f, 0.f);
            if (row0 + r < nrows) v = ((const float4*)(A + (size_t)(row0 + r) * DD))[c4];
            As4[idx] = v;
        }
    }
    __syncthreads();

    const int tc = tid & 31;   // 4 cols: tc*4 .. tc*4+3
    const int tr = tid >> 5;   // 8 rows: tr*8 .. tr*8+7
    unsigned long long acc[8][2];
    #pragma unroll
    for (int i = 0; i < 8; i++) { acc[i][0] = 0ull; acc[i][1] = 0ull; }

    const float4*     Arow = (const float4*)(As + tr * 8 * DD);  // broadcast reads
    const ulonglong2* Wsu  = ((const ulonglong2*)Ws) + tc;       // conflict-free LDS.128

    #pragma unroll 2
    for (int k4 = 0; k4 < 32; k4++) {
        float4 a[8];
        #pragma unroll
        for (int i = 0; i < 8; i++) a[i] = Arow[i * 32 + k4];
        #pragma unroll
        for (int kk = 0; kk < 4; kk++) {
            ulonglong2 wp = Wsu[(k4 * 4 + kk) * 32];
            #pragma unroll
            for (int i = 0; i < 8; i++) {
                float av = (kk == 0) ? a[i].x : (kk == 1) ? a[i].y : (kk == 2) ? a[i].z : a[i].w;
                unsigned long long ad = pack2(av, av);
                acc[i][0] = ffma2(ad, wp.x, acc[i][0]);
                acc[i][1] = ffma2(ad, wp.y, acc[i][1]);
            }
        }
    }

    // epilogue
    const int c0 = tc * 4;
    float bcol[4], sc[4], sh[4];
    #pragma unroll
    for (int j = 0; j < 4; j++) {
        bcol[j] = bias[c0 + j];
        if (EPI == 1) {
            float s = bng[c0 + j] * rsqrtf(bnv[c0 + j] + 1e-5f);
            sc[j] = s;
            sh[j] = bnb[c0 + j] - bnm[c0 + j] * s;
        }
    }
    #pragma unroll
    for (int i = 0; i < 8; i++) {
        int r = row0 + tr * 8 + i;
        if (r >= nrows) continue;
        float2 v0 = unpack2(acc[i][0]);
        float2 v1 = unpack2(acc[i][1]);
        float  vv[4] = {v0.x, v0.y, v1.x, v1.y};
        float4 o;
        float* op = (float*)&o;
        #pragma unroll
        for (int j = 0; j < 4; j++) {
            float t = vv[j] + bcol[j];
            if (EPI == 1) { t = t * sc[j] + sh[j]; t = hsw(t); }
            if (EPI == 2) { t = hsw(t); }
            op[j] = t;
        }
        ((float4*)(out + (size_t)r * DD))[tc] = o;
    }
}

// ---------------- head: logits = h2 @ Wp2 + bp2, then log_softmax -------------
__global__ void __launch_bounds__(256)
head_kernel(const float* __restrict__ h2, const float* __restrict__ Wp2,
            const float* __restrict__ bp2, float* __restrict__ out, int n) {
    extern __shared__ char smraw[];
    unsigned long long* wsh = (unsigned long long*)smraw;          // 128*20 packed pairs
    float* shh = (float*)(smraw + DD * 20 * sizeof(unsigned long long));  // 256*129
    const int tid = threadIdx.x;
    const int r0  = blockIdx.x * 256;

    for (int idx = tid; idx < DD * 20; idx += 256) {
        int k = idx / 20, j = idx % 20;
        wsh[idx] = pack2(Wp2[k * CC + 2 * j], Wp2[k * CC + 2 * j + 1]);
    }
    for (int idx = tid; idx < 256 * 32; idx += 256) {
        int lr = idx >> 5, c4 = idx & 31;
        float4 v = make_float4(0.f, 0.f, 0.f, 0.f);
        if (r0 + lr < n) v = ((const float4*)(h2 + (size_t)(r0 + lr) * DD))[c4];
        shh[lr * 129 + c4 * 4 + 0] = v.x;
        shh[lr * 129 + c4 * 4 + 1] = v.y;
        shh[lr * 129 + c4 * 4 + 2] = v.z;
        shh[lr * 129 + c4 * 4 + 3] = v.w;
    }
    __syncthreads();

    int r = r0 + tid;
    if (r >= n) return;
    unsigned long long acc[20];
    #pragma unroll
    for (int j = 0; j < 20; j++) acc[j] = pack2(bp2[2 * j], bp2[2 * j + 1]);

    const float* hr = shh + tid * 129;  // stride 129 -> conflict-free
    #pragma unroll 4
    for (int k = 0; k < DD; k++) {
        float a = hr[k];
        unsigned long long ad = pack2(a, a);
        const unsigned long long* wr = wsh + k * 20;  // broadcast reads
        #pragma unroll
        for (int j = 0; j < 20; j++) acc[j] = ffma2(ad, wr[j], acc[j]);
    }

    float vals[CC];
    #pragma unroll
    for (int j = 0; j < 20; j++) {
        float2 p = unpack2(acc[j]);
        vals[2 * j] = p.x;
        vals[2 * j + 1] = p.y;
    }
    float mx = vals[0];
    #pragma unroll
    for (int c = 1; c < CC; c++) mx = fmaxf(mx, vals[c]);
    float s = 0.f;
    #pragma unroll
    for (int c = 0; c < CC; c++) s += __expf(vals[c] - mx);
    float lse = mx + logf(s);
    #pragma unroll
    for (int c = 0; c < CC; c++) out[(size_t)r * CC + c] = vals[c] - lse;
}

// ---------------- launch orchestration ----------------
extern "C" void kernel_launch(void* const* d_in, const int* in_sizes, int n_in,
                              void* d_out, int out_size) {
    const float* x   = (const float*)d_in[0];
    const int*   src = (const int*)d_in[1];
    const int*   dst = (const int*)d_in[2];
    const float* Wg  = (const float*)d_in[3];
    const float* bg  = (const float*)d_in[4];
    const float* Wt  = (const float*)d_in[5];
    const float* bt  = (const float*)d_in[6];
    const float* W1  = (const float*)d_in[7];
    const float* b1  = (const float*)d_in[8];
    const float* bng = (const float*)d_in[9];
    const float* bnb = (const float*)d_in[10];
    const float* bnm = (const float*)d_in[11];
    const float* bnv = (const float*)d_in[12];
    const float* W2  = (const float*)d_in[13];
    const float* b2  = (const float*)d_in[14];
    const float* Wp1 = (const float*)d_in[15];
    const float* bp1 = (const float*)d_in[16];
    const float* Wp2 = (const float*)d_in[17];
    const float* bp2 = (const float*)d_in[18];
    float* out = (float*)d_out;

    const int n = in_sizes[0] / DD;
    const int e = in_sizes[1];

    float *ph, *pht, *pagg, *pg;
    int *prow, *pcur, *psrc;
    cudaGetSymbolAddress((void**)&ph,   g_h);
    cudaGetSymbolAddress((void**)&pht,  g_ht);
    cudaGetSymbolAddress((void**)&pagg, g_agg);
    cudaGetSymbolAddress((void**)&pg,   g_gate);
    cudaGetSymbolAddress((void**)&prow, g_rowptr);
    cudaGetSymbolAddress((void**)&pcur, g_cursor);
    cudaGetSymbolAddress((void**)&psrc, g_srcs);

    const int GEMM_SMEM = (DD * DD + 64 * DD) * (int)sizeof(float);          // 96 KB
    const int HEAD_SMEM = DD * 20 * (int)sizeof(unsigned long long)
                        + 256 * 129 * (int)sizeof(float);                    // ~149 KB
    cudaFuncSetAttribute(gemm128<0>, cudaFuncAttributeMaxDynamicSharedMemorySize, GEMM_SMEM);
    cudaFuncSetAttribute(gemm128<1>, cudaFuncAttributeMaxDynamicSharedMemorySize, GEMM_SMEM);
    cudaFuncSetAttribute(gemm128<2>, cudaFuncAttributeMaxDynamicSharedMemorySize, GEMM_SMEM);
    cudaFuncSetAttribute(head_kernel, cudaFuncAttributeMaxDynamicSharedMemorySize, HEAD_SMEM);

    // CSR build (dst-sorted incoming edge lists, self-loops included)
    init_deg_kernel<<<(n + 255) / 256, 256>>>(pcur, n);
    count_kernel<<<(e + 255) / 256, 256>>>(dst, pcur, e);
    scan_kernel<<<1, 1024>>>(pcur, prow, n);
    scatter_kernel<<<(e + n + 255) / 256, 256>>>(src, dst, pcur, psrc, e, n);

    const int gblocks = (n + 63) / 64;
    const int wblocks = (n * 32 + 255) / 256;

    for (int i = 0; i < LL; i++) {
        const float* hin = (i == 0) ? x : ph;
        gate_kernel<<<wblocks, 256>>>(hin, Wg + (size_t)i * DD, bg + i, pg, n);
        gemm128<0><<<gblocks, 256, GEMM_SMEM>>>(hin, Wt + (size_t)i * DD * DD,
                                                bt + (size_t)i * DD,
                                                nullptr, nullptr, nullptr, nullptr, pht, n);
        edge_agg_kernel<<<wblocks, 256>>>(prow, psrc, pg, pht, pagg, n);
        gemm128<1><<<gblocks, 256, GEMM_SMEM>>>(pagg, W1 + (size_t)i * DD * DD,
                                                b1 + (size_t)i * DD,
                                                bng + (size_t)i * DD, bnb + (size_t)i * DD,
                                                bnm + (size_t)i * DD, bnv + (size_t)i * DD,
                                                pht, n);
        gemm128<2><<<gblocks, 256, GEMM_SMEM>>>(pht, W2 + (size_t)i * DD * DD,
                                                b2 + (size_t)i * DD,
                                                nullptr, nullptr, nullptr, nullptr, ph, n);
    }
    gemm128<2><<<gblocks, 256, GEMM_SMEM>>>(ph, Wp1, bp1,
                                            nullptr, nullptr, nullptr, nullptr, pht, n);
    head_kernel<<<(n + 255) / 256, 256, HEAD_SMEM>>>(pht, Wp2, bp2, out, n);
}

// round 6
// speedup vs baseline: 1.0025x; 1.0025x over previous
#include <cuda_runtime.h>

#define NN 50000
#define DD 128
#define EE 600000
#define CC 40
#define LL 4

// ---------------- scratch (static device globals; no allocation) ----------------
__device__ float g_ht [NN * DD];
__device__ float g_agg[NN * DD];
__device__ float g_gate[NN];
__device__ int   g_rowptr[NN + 1];
__device__ int   g_cursor[NN];
__device__ int   g_srcs[EE + NN];

// ---------------- helpers ----------------
__device__ __forceinline__ unsigned long long ffma2(unsigned long long a,
                                                    unsigned long long b,
                                                    unsigned long long c) {
    unsigned long long d;
    asm("fma.rn.f32x2 %0, %1, %2, %3;" : "=l"(d) : "l"(a), "l"(b), "l"(c));
    return d;
}
__device__ __forceinline__ unsigned long long pack2(float x, float y) {
    unsigned long long r;
    asm("mov.b64 %0, {%1, %2};" : "=l"(r) : "f"(x), "f"(y));
    return r;
}
__device__ __forceinline__ float2 unpack2(unsigned long long v) {
    float2 f;
    asm("mov.b64 {%0, %1}, %2;" : "=f"(f.x), "=f"(f.y) : "l"(v));
    return f;
}
__device__ __forceinline__ float hsw(float x) {
    return x * fminf(fmaxf(x + 3.f, 0.f), 6.f) * (1.f / 6.f);
}

// ---------------- CSR build ----------------
__global__ void init_deg_kernel(int* __restrict__ cursor, int n) {
    int i = blockIdx.x * blockDim.x + threadIdx.x;
    if (i < n) cursor[i] = 1;  // self loop
}

__global__ void count_kernel(const int* __restrict__ dst, int* __restrict__ cursor, int e) {
    int i = blockIdx.x * blockDim.x + threadIdx.x;
    if (i < e) atomicAdd(&cursor[dst[i]], 1);
}

__global__ void scan_kernel(int* __restrict__ cursor, int* __restrict__ rowptr, int n) {
    __shared__ int wsum[32];
    const int lane = threadIdx.x & 31;
    const int wid  = threadIdx.x >> 5;
    int carry = 0;
    for (int base = 0; base < n; base += 1024) {
        int i = base + threadIdx.x;
        int v = (i < n) ? cursor[i] : 0;
        int x = v;
        #pragma unroll
        for (int o = 1; o < 32; o <<= 1) {
            int y = __shfl_up_sync(0xffffffffu, x, o);
            if (lane >= o) x += y;
        }
        if (lane == 31) wsum[wid] = x;
        __syncthreads();
        if (wid == 0) {
            int s = wsum[lane];
            #pragma unroll
            for (int o = 1; o < 32; o <<= 1) {
                int y = __shfl_up_sync(0xffffffffu, s, o);
                if (lane >= o) s += y;
            }
            wsum[lane] = s;
        }
        __syncthreads();
        int off  = carry + (wid ? wsum[wid - 1] : 0);
        int excl = off + x - v;
        if (i < n) { rowptr[i] = excl; cursor[i] = excl; }
        carry += wsum[31];
        __syncthreads();
    }
    if (threadIdx.x == 0) rowptr[n] = carry;
}

__global__ void scatter_kernel(const int* __restrict__ src, const int* __restrict__ dst,
                               int* __restrict__ cursor, int* __restrict__ srcs,
                               int e, int n) {
    int i = blockIdx.x * blockDim.x + threadIdx.x;
    if (i >= e + n) return;
    int d, s;
    if (i < e) { d = dst[i]; s = src[i]; }
    else       { d = i - e;  s = i - e;  }
    int p = atomicAdd(&cursor[d], 1);
    srcs[p] = s;
}

// ---------------- fused softmax-attention aggregation (warp per dst node) -----
__global__ void __launch_bounds__(256)
edge_agg_kernel(const int* __restrict__ rowptr, const int* __restrict__ srcs,
                const float* __restrict__ g, const float* __restrict__ ht,
                float* __restrict__ agg, int n) {
    int gt   = blockIdx.x * blockDim.x + threadIdx.x;
    int w    = gt >> 5;
    int lane = gt & 31;
    if (w >= n) return;
    int beg = rowptr[w];
    int end = rowptr[w + 1];

    // single-pass online softmax stats (m, s)
    float m = -3.4e38f, s = 0.f;
    for (int j = beg + lane; j < end; j += 32) {
        float gi = g[srcs[j]];
        float mn = fmaxf(m, gi);
        s = s * __expf(m - mn) + __expf(gi - mn);
        m = mn;
    }
    #pragma unroll
    for (int o = 16; o; o >>= 1) {
        float om = __shfl_xor_sync(0xffffffffu, m, o);
        float os = __shfl_xor_sync(0xffffffffu, s, o);
        float mn = fmaxf(m, om);
        s = s * __expf(m - mn) + os * __expf(om - mn);
        m = mn;
    }
    float inv = 1.f / s;

    float4 acc0 = make_float4(0.f, 0.f, 0.f, 0.f);
    float4 acc1 = make_float4(0.f, 0.f, 0.f, 0.f);
    int j = beg;
    for (; j + 1 < end; j += 2) {
        int   s0 = srcs[j], s1 = srcs[j + 1];
        float w0 = __expf(g[s0] - m) * inv;
        float w1 = __expf(g[s1] - m) * inv;
        float4 v0 = ((const float4*)(ht + (size_t)s0 * DD))[lane];
        float4 v1 = ((const float4*)(ht + (size_t)s1 * DD))[lane];
        acc0.x = fmaf(w0, v0.x, acc0.x); acc1.x = fmaf(w1, v1.x, acc1.x);
        acc0.y = fmaf(w0, v0.y, acc0.y); acc1.y = fmaf(w1, v1.y, acc1.y);
        acc0.z = fmaf(w0, v0.z, acc0.z); acc1.z = fmaf(w1, v1.z, acc1.z);
        acc0.w = fmaf(w0, v0.w, acc0.w); acc1.w = fmaf(w1, v1.w, acc1.w);
    }
    if (j < end) {
        int   s0 = srcs[j];
        float w0 = __expf(g[s0] - m) * inv;
        float4 v0 = ((const float4*)(ht + (size_t)s0 * DD))[lane];
        acc0.x = fmaf(w0, v0.x, acc0.x);
        acc0.y = fmaf(w0, v0.y, acc0.y);
        acc0.z = fmaf(w0, v0.z, acc0.z);
        acc0.w = fmaf(w0, v0.w, acc0.w);
    }
    acc0.x += acc1.x; acc0.y += acc1.y; acc0.z += acc1.z; acc0.w += acc1.w;
    ((float4*)(agg + (size_t)w * DD))[lane] = acc0;
}

// ---------------- core 64x128 @ 128x128 tile MMA (smem -> regs) ---------------
__device__ __forceinline__ void mm_stage(const float* __restrict__ As,
                                         const float* __restrict__ Ws,
                                         unsigned long long acc[8][2],
                                         int tr, int tc) {
    #pragma unroll
    for (int i = 0; i < 8; i++) { acc[i][0] = 0ull; acc[i][1] = 0ull; }
    const float4*     Arow = (const float4*)(As + tr * 8 * DD);
    const ulonglong2* Wsu  = ((const ulonglong2*)Ws) + tc;
    #pragma unroll 2
    for (int k4 = 0; k4 < 32; k4++) {
        float4 a[8];
        #pragma unroll
        for (int i = 0; i < 8; i++) a[i] = Arow[i * 32 + k4];
        #pragma unroll
        for (int kk = 0; kk < 4; kk++) {
            ulonglong2 wp = Wsu[(k4 * 4 + kk) * 32];
            #pragma unroll
            for (int i = 0; i < 8; i++) {
                float av = (kk == 0) ? a[i].x : (kk == 1) ? a[i].y : (kk == 2) ? a[i].z : a[i].w;
                unsigned long long ad = pack2(av, av);
                acc[i][0] = ffma2(ad, wp.x, acc[i][0]);
                acc[i][1] = ffma2(ad, wp.y, acc[i][1]);
            }
        }
    }
}

// ---------------- fused per-layer node chain (persistent, 1 block/SM) --------
// stage1: z  = hsw(BN(A @ W1 + b1))
// stage2: h  = hsw(z @ W2 + b2)
// stage3 (LAST=0): out = h @ W3(=Wt) + b3(=bt);  gate = h . Wg + bg
// stage3 (LAST=1): out = hsw(h @ W3(=Wp1) + b3(=bp1))
template <int LAST>
__global__ void __launch_bounds__(256)
chain3(const float* __restrict__ A,
       const float* __restrict__ W1, const float* __restrict__ b1,
       const float* __restrict__ bng, const float* __restrict__ bnb,
       const float* __restrict__ bnm, const float* __restrict__ bnv,
       const float* __restrict__ W2, const float* __restrict__ b2,
       const float* __restrict__ W3, const float* __restrict__ b3,
       const float* __restrict__ Wg, const float* __restrict__ bg,
       float* __restrict__ outA, float* __restrict__ gate, int nrows) {
    extern __shared__ float sm[];
    float* W1s = sm;
    float* W2s = sm + 16384;
    float* W3s = sm + 32768;
    float* As  = sm + 49152;
    const int tid = threadIdx.x;
    const int tc  = tid & 31;
    const int tr  = tid >> 5;

    {   // stage all three weight matrices once per block
        const float4 *w1 = (const float4*)W1, *w2 = (const float4*)W2, *w3 = (const float4*)W3;
        float4 *s1 = (float4*)W1s, *s2 = (float4*)W2s, *s3 = (float4*)W3s;
        #pragma unroll
        for (int it = 0; it < 16; it++) {
            s1[it * 256 + tid] = w1[it * 256 + tid];
            s2[it * 256 + tid] = w2[it * 256 + tid];
            s3[it * 256 + tid] = w3[it * 256 + tid];
        }
    }

    // per-thread epilogue constants (fixed 4 columns)
    const int c0 = tc * 4;
    float b1c[4], scc[4], shc[4], b2c[4], b3c[4];
    #pragma unroll
    for (int j = 0; j < 4; j++) {
        b1c[j] = b1[c0 + j];
        float sv = bng[c0 + j] * rsqrtf(bnv[c0 + j] + 1e-5f);
        scc[j] = sv;
        shc[j] = bnb[c0 + j] - bnm[c0 + j] * sv;
        b2c[j] = b2[c0 + j];
        b3c[j] = b3[c0 + j];
    }
    float4 wgv = make_float4(0.f, 0.f, 0.f, 0.f);
    float bg0 = 0.f;
    if (!LAST) { wgv = ((const float4*)Wg)[tc]; bg0 = bg[0]; }

    const int ntiles = (nrows + 63) >> 6;
    int t = blockIdx.x;
    if (t < ntiles) {   // load first tile
        float4* As4 = (float4*)As;
        #pragma unroll
        for (int it = 0; it < 8; it++) {
            int idx = it * 256 + tid;
            int r = idx >> 5, c4 = idx & 31;
            int gr = t * 64 + r;
            float4 v = make_float4(0.f, 0.f, 0.f, 0.f);
            if (gr < nrows) v = ((const float4*)(A + (size_t)gr * DD))[c4];
            As4[idx] = v;
        }
    }

    for (; t < ntiles; t += gridDim.x) {
        __syncthreads();
        unsigned long long acc[8][2];
        float z[8][4];

        // ---- stage 1 ----
        mm_stage(As, W1s, acc, tr, tc);
        #pragma unroll
        for (int i = 0; i < 8; i++) {
            float2 v0 = unpack2(acc[i][0]), v1 = unpack2(acc[i][1]);
            float vv[4] = {v0.x, v0.y, v1.x, v1.y};
            #pragma unroll
            for (int j = 0; j < 4; j++) {
                float q = vv[j] + b1c[j];
                q = q * scc[j] + shc[j];
                z[i][j] = hsw(q);
            }
        }
        __syncthreads();
        #pragma unroll
        for (int i = 0; i < 8; i++)
            ((float4*)(As + (tr * 8 + i) * DD))[tc] = make_float4(z[i][0], z[i][1], z[i][2], z[i][3]);
        __syncthreads();

        // ---- stage 2 ----
        mm_stage(As, W2s, acc, tr, tc);
        #pragma unroll
        for (int i = 0; i < 8; i++) {
            float2 v0 = unpack2(acc[i][0]), v1 = unpack2(acc[i][1]);
            float vv[4] = {v0.x, v0.y, v1.x, v1.y};
            #pragma unroll
            for (int j = 0; j < 4; j++) z[i][j] = hsw(vv[j] + b2c[j]);
        }
        __syncthreads();
        #pragma unroll
        for (int i = 0; i < 8; i++)
            ((float4*)(As + (tr * 8 + i) * DD))[tc] = make_float4(z[i][0], z[i][1], z[i][2], z[i][3]);
        __syncthreads();

        // ---- prefetch next A tile into registers (overlaps stage 3) ----
        const int tn = t + gridDim.x;
        float4 pf[8];
        if (tn < ntiles) {
            #pragma unroll
            for (int it = 0; it < 8; it++) {
                int idx = it * 256 + tid;
                int r = idx >> 5, c4 = idx & 31;
                int gr = tn * 64 + r;
                pf[it] = (gr < nrows) ? ((const float4*)(A + (size_t)gr * DD))[c4]
                                      : make_float4(0.f, 0.f, 0.f, 0.f);
            }
        }

        // ---- stage 3 ----
        mm_stage(As, W3s, acc, tr, tc);
        if (!LAST) {
            // gate = h . Wg + bg (h still in As)
            #pragma unroll
            for (int i = 0; i < 8; i++) {
                float4 hv = ((const float4*)(As + (tr * 8 + i) * DD))[tc];
                float p = hv.x * wgv.x + hv.y * wgv.y + hv.z * wgv.z + hv.w * wgv.w;
                #pragma unroll
                for (int o = 16; o; o >>= 1) p += __shfl_xor_sync(0xffffffffu, p, o);
                int gr = t * 64 + tr * 8 + i;
                if (tc == 0 && gr < nrows) gate[gr] = p + bg0;
            }
        }
        #pragma unroll
        for (int i = 0; i < 8; i++) {
            int gr = t * 64 + tr * 8 + i;
            if (gr >= nrows) continue;
            float2 v0 = unpack2(acc[i][0]), v1 = unpack2(acc[i][1]);
            float vv[4] = {v0.x, v0.y, v1.x, v1.y};
            float4 o;
            float* op = (float*)&o;
            #pragma unroll
            for (int j = 0; j < 4; j++) {
                float q = vv[j] + b3c[j];
                if (LAST) q = hsw(q);
                op[j] = q;
            }
            ((float4*)(outA + (size_t)gr * DD))[tc] = o;
        }
        __syncthreads();
        if (tn < ntiles) {
            float4* As4 = (float4*)As;
            #pragma unroll
            for (int it = 0; it < 8; it++) As4[it * 256 + tid] = pf[it];
        }
    }
}

// ---------------- layer-0 front: ht = x@Wt+bt, gate = x.Wg+bg (persistent) ----
__global__ void __launch_bounds__(256, 2)
gemm_gate(const float* __restrict__ A, const float* __restrict__ W,
          const float* __restrict__ bias,
          const float* __restrict__ Wg, const float* __restrict__ bg,
          float* __restrict__ ht, float* __restrict__ gate, int nrows) {
    extern __shared__ float sm[];
    float* Ws = sm;
    float* As = sm + 16384;
    const int tid = threadIdx.x;
    const int tc  = tid & 31;
    const int tr  = tid >> 5;

    {
        const float4* w = (const float4*)W;
        float4* s = (float4*)Ws;
        #pragma unroll
        for (int it = 0; it < 16; it++) s[it * 256 + tid] = w[it * 256 + tid];
    }
    const int c0 = tc * 4;
    float bc[4];
    #pragma unroll
    for (int j = 0; j < 4; j++) bc[j] = bias[c0 + j];
    float4 wgv = ((const float4*)Wg)[tc];
    float bg0 = bg[0];

    const int ntiles = (nrows + 63) >> 6;
    for (int t = blockIdx.x; t < ntiles; t += gridDim.x) {
        {
            float4* As4 = (float4*)As;
            #pragma unroll
            for (int it = 0; it < 8; it++) {
                int idx = it * 256 + tid;
                int r = idx >> 5, c4 = idx & 31;
                int gr = t * 64 + r;
                float4 v = make_float4(0.f, 0.f, 0.f, 0.f);
                if (gr < nrows) v = ((const float4*)(A + (size_t)gr * DD))[c4];
                As4[idx] = v;
            }
        }
        __syncthreads();
        unsigned long long acc[8][2];
        mm_stage(As, Ws, acc, tr, tc);
        // gate from input x (in As)
        #pragma unroll
        for (int i = 0; i < 8; i++) {
            float4 hv = ((const float4*)(As + (tr * 8 + i) * DD))[tc];
            float p = hv.x * wgv.x + hv.y * wgv.y + hv.z * wgv.z + hv.w * wgv.w;
            #pragma unroll
            for (int o = 16; o; o >>= 1) p += __shfl_xor_sync(0xffffffffu, p, o);
            int gr = t * 64 + tr * 8 + i;
            if (tc == 0 && gr < nrows) gate[gr] = p + bg0;
        }
        #pragma unroll
        for (int i = 0; i < 8; i++) {
            int gr = t * 64 + tr * 8 + i;
            if (gr >= nrows) continue;
            float2 v0 = unpack2(acc[i][0]), v1 = unpack2(acc[i][1]);
            float4 o = make_float4(v0.x + bc[0], v0.y + bc[1], 0.f, 0.f);
            float2 v1u = v1;
            o.z = v1u.x + bc[2];
            o.w = v1u.y + bc[3];
            ((float4*)(ht + (size_t)gr * DD))[tc] = o;
        }
        __syncthreads();
    }
}

// ---------------- head: logits = h2 @ Wp2 + bp2, then log_softmax -------------
__global__ void __launch_bounds__(256)
head_kernel(const float* __restrict__ h2, const float* __restrict__ Wp2,
            const float* __restrict__ bp2, float* __restrict__ out, int n) {
    extern __shared__ char smraw[];
    unsigned long long* wsh = (unsigned long long*)smraw;          // 128*20 packed pairs
    float* shh = (float*)(smraw + DD * 20 * sizeof(unsigned long long));  // 256*129
    const int tid = threadIdx.x;
    const int r0  = blockIdx.x * 256;

    for (int idx = tid; idx < DD * 20; idx += 256) {
        int k = idx / 20, j = idx % 20;
        wsh[idx] = pack2(Wp2[k * CC + 2 * j], Wp2[k * CC + 2 * j + 1]);
    }
    for (int idx = tid; idx < 256 * 32; idx += 256) {
        int lr = idx >> 5, c4 = idx & 31;
        float4 v = make_float4(0.f, 0.f, 0.f, 0.f);
        if (r0 + lr < n) v = ((const float4*)(h2 + (size_t)(r0 + lr) * DD))[c4];
        shh[lr * 129 + c4 * 4 + 0] = v.x;
        shh[lr * 129 + c4 * 4 + 1] = v.y;
        shh[lr * 129 + c4 * 4 + 2] = v.z;
        shh[lr * 129 + c4 * 4 + 3] = v.w;
    }
    __syncthreads();

    int r = r0 + tid;
    if (r >= n) return;
    unsigned long long acc[20];
    #pragma unroll
    for (int j = 0; j < 20; j++) acc[j] = pack2(bp2[2 * j], bp2[2 * j + 1]);

    const float* hr = shh + tid * 129;
    #pragma unroll 4
    for (int k = 0; k < DD; k++) {
        float a = hr[k];
        unsigned long long ad = pack2(a, a);
        const unsigned long long* wr = wsh + k * 20;
        #pragma unroll
        for (int j = 0; j < 20; j++) acc[j] = ffma2(ad, wr[j], acc[j]);
    }

    float vals[CC];
    #pragma unroll
    for (int j = 0; j < 20; j++) {
        float2 p = unpack2(acc[j]);
        vals[2 * j] = p.x;
        vals[2 * j + 1] = p.y;
    }
    float mx = vals[0];
    #pragma unroll
    for (int c = 1; c < CC; c++) mx = fmaxf(mx, vals[c]);
    float s = 0.f;
    #pragma unroll
    for (int c = 0; c < CC; c++) s += __expf(vals[c] - mx);
    float lse = mx + logf(s);
    #pragma unroll
    for (int c = 0; c < CC; c++) out[(size_t)r * CC + c] = vals[c] - lse;
}

// ---------------- launch orchestration ----------------
extern "C" void kernel_launch(void* const* d_in, const int* in_sizes, int n_in,
                              void* d_out, int out_size) {
    const float* x   = (const float*)d_in[0];
    const int*   src = (const int*)d_in[1];
    const int*   dst = (const int*)d_in[2];
    const float* Wg  = (const float*)d_in[3];
    const float* bg  = (const float*)d_in[4];
    const float* Wt  = (const float*)d_in[5];
    const float* bt  = (const float*)d_in[6];
    const float* W1  = (const float*)d_in[7];
    const float* b1  = (const float*)d_in[8];
    const float* bng = (const float*)d_in[9];
    const float* bnb = (const float*)d_in[10];
    const float* bnm = (const float*)d_in[11];
    const float* bnv = (const float*)d_in[12];
    const float* W2  = (const float*)d_in[13];
    const float* b2  = (const float*)d_in[14];
    const float* Wp1 = (const float*)d_in[15];
    const float* bp1 = (const float*)d_in[16];
    const float* Wp2 = (const float*)d_in[17];
    const float* bp2 = (const float*)d_in[18];
    float* out = (float*)d_out;

    const int n = in_sizes[0] / DD;
    const int e = in_sizes[1];

    float *pht, *pagg, *pg;
    int *prow, *pcur, *psrc;
    cudaGetSymbolAddress((void**)&pht,  g_ht);
    cudaGetSymbolAddress((void**)&pagg, g_agg);
    cudaGetSymbolAddress((void**)&pg,   g_gate);
    cudaGetSymbolAddress((void**)&prow, g_rowptr);
    cudaGetSymbolAddress((void**)&pcur, g_cursor);
    cudaGetSymbolAddress((void**)&psrc, g_srcs);

    const int CHAIN_SMEM = (3 * DD * DD + 64 * DD) * (int)sizeof(float);   // 224 KB
    const int GG_SMEM    = (DD * DD + 64 * DD) * (int)sizeof(float);       // 96 KB
    const int HEAD_SMEM  = DD * 20 * (int)sizeof(unsigned long long)
                         + 256 * 129 * (int)sizeof(float);
    cudaFuncSetAttribute(chain3<0>, cudaFuncAttributeMaxDynamicSharedMemorySize, CHAIN_SMEM);
    cudaFuncSetAttribute(chain3<1>, cudaFuncAttributeMaxDynamicSharedMemorySize, CHAIN_SMEM);
    cudaFuncSetAttribute(gemm_gate, cudaFuncAttributeMaxDynamicSharedMemorySize, GG_SMEM);
    cudaFuncSetAttribute(head_kernel, cudaFuncAttributeMaxDynamicSharedMemorySize, HEAD_SMEM);

    // CSR build (dst-sorted incoming edge lists, self-loops included)
    init_deg_kernel<<<(n + 255) / 256, 256>>>(pcur, n);
    count_kernel<<<(e + 255) / 256, 256>>>(dst, pcur, e);
    scan_kernel<<<1, 1024>>>(pcur, prow, n);
    scatter_kernel<<<(e + n + 255) / 256, 256>>>(src, dst, pcur, psrc, e, n);

    const int wblocks = (n * 32 + 255) / 256;
    const int PERS1 = 148;          // 1 block/SM persistent
    const int PERS2 = 296;          // 2 blocks/SM persistent

    // layer 0 front: gate/ht from x
    gemm_gate<<<PERS2, 256, GG_SMEM>>>(x, Wt, bt, Wg, bg, pht, pg, n);

    for (int i = 0; i < LL; i++) {
        edge_agg_kernel<<<wblocks, 256>>>(prow, psrc, pg, pht, pagg, n);
        if (i < LL - 1) {
            chain3<0><<<PERS1, 256, CHAIN_SMEM>>>(
                pagg,
                W1 + (size_t)i * DD * DD, b1 + (size_t)i * DD,
                bng + (size_t)i * DD, bnb + (size_t)i * DD,
                bnm + (size_t)i * DD, bnv + (size_t)i * DD,
                W2 + (size_t)i * DD * DD, b2 + (size_t)i * DD,
                Wt + (size_t)(i + 1) * DD * DD, bt + (size_t)(i + 1) * DD,
                Wg + (size_t)(i + 1) * DD, bg + (i + 1),
                pht, pg, n);
        } else {
            chain3<1><<<PERS1, 256, CHAIN_SMEM>>>(
                pagg,
                W1 + (size_t)i * DD * DD, b1 + (size_t)i * DD,
                bng + (size_t)i * DD, bnb + (size_t)i * DD,
                bnm + (size_t)i * DD, bnv + (size_t)i * DD,
                W2 + (size_t)i * DD * DD, b2 + (size_t)i * DD,
                Wp1, bp1,
                nullptr, nullptr,
                pht, nullptr, n);
        }
    }
    head_kernel<<<(n + 255) / 256, 256, HEAD_SMEM>>>(pht, Wp2, bp2, out, n);
}

// round 7
// speedup vs baseline: 1.0639x; 1.0613x over previous
#include <cuda_runtime.h>

#define NN 50000
#define DD 128
#define EE 600000
#define CC 40
#define LL 4

// ---------------- scratch (static device globals; no allocation) ----------------
__device__ __align__(16) float g_h  [NN * DD];
__device__ __align__(16) float g_agg[NN * DD];
__device__ __align__(16) float g_gate[NN];
__device__ __align__(16) int   g_rowptr[NN + 4];
__device__ __align__(16) int   g_cursor[NN];
__device__ __align__(16) int   g_srcs[EE + NN];

// ---------------- helpers ----------------
__device__ __forceinline__ unsigned long long ffma2(unsigned long long a,
                                                    unsigned long long b,
                                                    unsigned long long c) {
    unsigned long long d;
    asm("fma.rn.f32x2 %0, %1, %2, %3;" : "=l"(d) : "l"(a), "l"(b), "l"(c));
    return d;
}
__device__ __forceinline__ unsigned long long pack2(float x, float y) {
    unsigned long long r;
    asm("mov.b64 %0, {%1, %2};" : "=l"(r) : "f"(x), "f"(y));
    return r;
}
__device__ __forceinline__ float2 unpack2(unsigned long long v) {
    float2 f;
    asm("mov.b64 {%0, %1}, %2;" : "=f"(f.x), "=f"(f.y) : "l"(v));
    return f;
}
__device__ __forceinline__ float hsw(float x) {
    return x * fminf(fmaxf(x + 3.f, 0.f), 6.f) * (1.f / 6.f);
}

// ---------------- CSR build ----------------
// counts incoming edges + implicit self-loops (cursor pre-zeroed via memset)
__global__ void count_ext_kernel(const int* __restrict__ dst, int* __restrict__ cursor,
                                 int e, int n) {
    int i = blockIdx.x * blockDim.x + threadIdx.x;
    if (i >= e + n) return;
    int d = (i < e) ? dst[i] : (i - e);
    atomicAdd(&cursor[d], 1);
}

// single-block exclusive scan, int4-vectorized (13 iterations for n=50000)
__global__ void scan_kernel(int* __restrict__ cursor, int* __restrict__ rowptr, int n) {
    __shared__ int wsum[32];
    const int lane = threadIdx.x & 31;
    const int wid  = threadIdx.x >> 5;
    int carry = 0;
    for (int base = 0; base < n; base += 4096) {
        int idx = base + threadIdx.x * 4;
        int4 v = make_int4(0, 0, 0, 0);
        if (idx < n) v = *(const int4*)(cursor + idx);
        int t = v.x + v.y + v.z + v.w;
        int x = t;
        #pragma unroll
        for (int o = 1; o < 32; o <<= 1) {
            int y = __shfl_up_sync(0xffffffffu, x, o);
            if (lane >= o) x += y;
        }
        if (lane == 31) wsum[wid] = x;
        __syncthreads();
        if (wid == 0) {
            int s = wsum[lane];
            #pragma unroll
            for (int o = 1; o < 32; o <<= 1) {
                int y = __shfl_up_sync(0xffffffffu, s, o);
                if (lane >= o) s += y;
            }
            wsum[lane] = s;
        }
        __syncthreads();
        int excl = carry + (wid ? wsum[wid - 1] : 0) + x - t;
        if (idx < n) {
            int4 r;
            r.x = excl;
            r.y = excl + v.x;
            r.z = r.y + v.y;
            r.w = r.z + v.z;
            *(int4*)(rowptr + idx) = r;
            *(int4*)(cursor + idx) = r;
        }
        carry += wsum[31];
        __syncthreads();
    }
    if (threadIdx.x == 0) rowptr[n] = carry;
}

// scatter edges into CSR; extra blocks compute layer-0 gate = x.Wg0 + bg0
__global__ void __launch_bounds__(256)
scatter_gate_kernel(const int* __restrict__ src, const int* __restrict__ dst,
                    int* __restrict__ cursor, int* __restrict__ srcs,
                    const float* __restrict__ x, const float* __restrict__ Wg0,
                    const float* __restrict__ bg0, float* __restrict__ gate,
                    int e, int n, int SB) {
    if ((int)blockIdx.x < SB) {
        int i = blockIdx.x * 256 + threadIdx.x;
        if (i >= e + n) return;
        int d, s;
        if (i < e) { d = dst[i]; s = src[i]; }
        else       { d = i - e;  s = i - e;  }
        int p = atomicAdd(&cursor[d], 1);
        srcs[p] = s;
    } else {
        int bid2 = blockIdx.x - SB;
        int row  = bid2 * 8 + (threadIdx.x >> 5);
        int lane = threadIdx.x & 31;
        if (row >= n) return;
        float4 a = ((const float4*)(x + (size_t)row * DD))[lane];
        float4 b = ((const float4*)Wg0)[lane];
        float s  = a.x * b.x + a.y * b.y + a.z * b.z + a.w * b.w;
        #pragma unroll
        for (int o = 16; o; o >>= 1) s += __shfl_xor_sync(0xffffffffu, s, o);
        if (lane == 0) gate[row] = s + bg0[0];
    }
}

// ---------------- fused softmax-attention aggregation (warp per dst node) -----
// aggregates RAW feature rows (transform commuted to after aggregation)
__global__ void __launch_bounds__(256)
edge_agg_kernel(const int* __restrict__ rowptr, const int* __restrict__ srcs,
                const float* __restrict__ g, const float* __restrict__ h,
                float* __restrict__ agg, int n) {
    int gt   = blockIdx.x * blockDim.x + threadIdx.x;
    int w    = gt >> 5;
    int lane = gt & 31;
    if (w >= n) return;
    int beg = rowptr[w];
    int end = rowptr[w + 1];

    // lane-parallel online softmax stats
    float m = -3.4e38f, s = 0.f;
    for (int j0 = beg; j0 < end; j0 += 32) {
        int  j  = j0 + lane;
        bool ok = (j < end);
        float gi = ok ? g[srcs[j]] : -3.4e38f;
        float mn = fmaxf(m, gi);
        s = s * __expf(m - mn) + (ok ? __expf(gi - mn) : 0.f);
        m = mn;
    }
    #pragma unroll
    for (int o = 16; o; o >>= 1) {
        float om = __shfl_xor_sync(0xffffffffu, m, o);
        float os = __shfl_xor_sync(0xffffffffu, s, o);
        float mn = fmaxf(m, om);
        s = s * __expf(m - mn) + os * __expf(om - mn);
        m = mn;
    }
    float inv = 1.f / s;

    float4 acc0 = make_float4(0.f, 0.f, 0.f, 0.f);
    float4 acc1 = make_float4(0.f, 0.f, 0.f, 0.f);
    for (int j0 = beg; j0 < end; j0 += 32) {
        int  j  = j0 + lane;
        bool ok = (j < end);
        int   sj  = ok ? srcs[j] : 0;
        float wgt = ok ? __expf(g[sj] - m) * inv : 0.f;
        int cnt = min(32, end - j0);
        int jj = 0;
        for (; jj + 1 < cnt; jj += 2) {
            float w0 = __shfl_sync(0xffffffffu, wgt, jj);
            float w1 = __shfl_sync(0xffffffffu, wgt, jj + 1);
            int   s0 = __shfl_sync(0xffffffffu, sj, jj);
            int   s1 = __shfl_sync(0xffffffffu, sj, jj + 1);
            float4 v0 = ((const float4*)(h + (size_t)s0 * DD))[lane];
            float4 v1 = ((const float4*)(h + (size_t)s1 * DD))[lane];
            acc0.x = fmaf(w0, v0.x, acc0.x); acc1.x = fmaf(w1, v1.x, acc1.x);
            acc0.y = fmaf(w0, v0.y, acc0.y); acc1.y = fmaf(w1, v1.y, acc1.y);
            acc0.z = fmaf(w0, v0.z, acc0.z); acc1.z = fmaf(w1, v1.z, acc1.z);
            acc0.w = fmaf(w0, v0.w, acc0.w); acc1.w = fmaf(w1, v1.w, acc1.w);
        }
        if (jj < cnt) {
            float w0 = __shfl_sync(0xffffffffu, wgt, jj);
            int   s0 = __shfl_sync(0xffffffffu, sj, jj);
            float4 v0 = ((const float4*)(h + (size_t)s0 * DD))[lane];
            acc0.x = fmaf(w0, v0.x, acc0.x);
            acc0.y = fmaf(w0, v0.y, acc0.y);
            acc0.z = fmaf(w0, v0.z, acc0.z);
            acc0.w = fmaf(w0, v0.w, acc0.w);
        }
    }
    acc0.x += acc1.x; acc0.y += acc1.y; acc0.z += acc1.z; acc0.w += acc1.w;
    ((float4*)(agg + (size_t)w * DD))[lane] = acc0;
}

// ---------------- core tile MMA: (R rows/thread) x 4 cols, smem -> regs -------
template <int R>
__device__ __forceinline__ void mm_stage(const float* __restrict__ As,
                                         const float* __restrict__ Ws,
                                         unsigned long long acc[R][2],
                                         int tr, int tc) {
    #pragma unroll
    for (int i = 0; i < R; i++) { acc[i][0] = 0ull; acc[i][1] = 0ull; }
    const float4*     Arow = (const float4*)(As + tr * R * DD);
    const ulonglong2* Wsu  = ((const ulonglong2*)Ws) + tc;
    #pragma unroll 2
    for (int k4 = 0; k4 < 32; k4++) {
        float4 a[R];
        #pragma unroll
        for (int i = 0; i < R; i++) a[i] = Arow[i * 32 + k4];
        #pragma unroll
        for (int kk = 0; kk < 4; kk++) {
            ulonglong2 wp = Wsu[(k4 * 4 + kk) * 32];
            #pragma unroll
            for (int i = 0; i < R; i++) {
                float av = (kk == 0) ? a[i].x : (kk == 1) ? a[i].y : (kk == 2) ? a[i].z : a[i].w;
                unsigned long long ad = pack2(av, av);
                acc[i][0] = ffma2(ad, wp.x, acc[i][0]);
                acc[i][1] = ffma2(ad, wp.y, acc[i][1]);
            }
        }
    }
}

// ---------------- fused per-layer chain (persistent, 512 thr, 1 blk/SM) -------
// stage1: t = xa @ Wt + bt          (transform commuted after aggregation)
// stage2: z = hsw(BN(t @ W1 + b1))
// stage3: h = hsw(z @ W2 + b2); (!LAST) gate_next = h . WgN + bgN
template <int LAST>
__global__ void __launch_bounds__(512)
chain3(const float* __restrict__ A,
       const float* __restrict__ Wt, const float* __restrict__ bt,
       const float* __restrict__ W1, const float* __restrict__ b1,
       const float* __restrict__ bng, const float* __restrict__ bnb,
       const float* __restrict__ bnm, const float* __restrict__ bnv,
       const float* __restrict__ W2, const float* __restrict__ b2,
       const float* __restrict__ WgN, const float* __restrict__ bgN,
       float* __restrict__ hout, float* __restrict__ gate, int nrows) {
    extern __shared__ float sm[];
    float* Wts = sm;
    float* W1s = sm + 16384;
    float* W2s = sm + 32768;
    float* As  = sm + 49152;
    const int tid = threadIdx.x;
    const int tc  = tid & 31;
    const int tr  = tid >> 5;          // 0..15, rows tr*4 .. tr*4+3

    {   // stage all three weight matrices once per block
        const float4 *wt = (const float4*)Wt, *w1 = (const float4*)W1, *w2 = (const float4*)W2;
        float4 *st = (float4*)Wts, *s1 = (float4*)W1s, *s2 = (float4*)W2s;
        #pragma unroll
        for (int it = 0; it < 8; it++) {
            st[it * 512 + tid] = wt[it * 512 + tid];
            s1[it * 512 + tid] = w1[it * 512 + tid];
            s2[it * 512 + tid] = w2[it * 512 + tid];
        }
    }

    const int c0 = tc * 4;
    float btc[4], b1c[4], scc[4], shc[4], b2c[4], wgc[4];
    #pragma unroll
    for (int j = 0; j < 4; j++) {
        btc[j] = bt[c0 + j];
        b1c[j] = b1[c0 + j];
        float sv = bng[c0 + j] * rsqrtf(bnv[c0 + j] + 1e-5f);
        scc[j] = sv;
        shc[j] = bnb[c0 + j] - bnm[c0 + j] * sv;
        b2c[j] = b2[c0 + j];
        wgc[j] = LAST ? 0.f : WgN[c0 + j];
    }
    float bg0 = LAST ? 0.f : bgN[0];

    const int ntiles = (nrows + 63) >> 6;
    int t = blockIdx.x;
    if (t < ntiles) {   // load first tile
        float4* As4 = (float4*)As;
        #pragma unroll
        for (int it = 0; it < 4; it++) {
            int idx = it * 512 + tid;
            int r = idx >> 5, c4 = idx & 31;
            int gr = t * 64 + r;
            float4 v = make_float4(0.f, 0.f, 0.f, 0.f);
            if (gr < nrows) v = ((const float4*)(A + (size_t)gr * DD))[c4];
            As4[idx] = v;
        }
    }

    for (; t < ntiles; t += gridDim.x) {
        __syncthreads();
        unsigned long long acc[4][2];
        float z[4][4];

        // ---- stage 1: @Wt + bt ----
        mm_stage<4>(As, Wts, acc, tr, tc);
        #pragma unroll
        for (int i = 0; i < 4; i++) {
            float2 v0 = unpack2(acc[i][0]), v1 = unpack2(acc[i][1]);
            z[i][0] = v0.x + btc[0]; z[i][1] = v0.y + btc[1];
            z[i][2] = v1.x + btc[2]; z[i][3] = v1.y + btc[3];
        }
        __syncthreads();
        #pragma unroll
        for (int i = 0; i < 4; i++)
            ((float4*)(As + (tr * 4 + i) * DD))[tc] = make_float4(z[i][0], z[i][1], z[i][2], z[i][3]);
        __syncthreads();

        // ---- stage 2: @W1 + b1, BN, hsw ----
        mm_stage<4>(As, W1s, acc, tr, tc);
        #pragma unroll
        for (int i = 0; i < 4; i++) {
            float2 v0 = unpack2(acc[i][0]), v1 = unpack2(acc[i][1]);
            float vv[4] = {v0.x, v0.y, v1.x, v1.y};
            #pragma unroll
            for (int j = 0; j < 4; j++) {
                float q = (vv[j] + b1c[j]) * scc[j] + shc[j];
                z[i][j] = hsw(q);
            }
        }
        __syncthreads();
        #pragma unroll
        for (int i = 0; i < 4; i++)
            ((float4*)(As + (tr * 4 + i) * DD))[tc] = make_float4(z[i][0], z[i][1], z[i][2], z[i][3]);
        __syncthreads();

        // ---- prefetch next A tile (overlaps stage 3) ----
        const int tn = t + gridDim.x;
        float4 pf[4];
        if (tn < ntiles) {
            #pragma unroll
            for (int it = 0; it < 4; it++) {
                int idx = it * 512 + tid;
                int r = idx >> 5, c4 = idx & 31;
                int gr = tn * 64 + r;
                pf[it] = (gr < nrows) ? ((const float4*)(A + (size_t)gr * DD))[c4]
                                      : make_float4(0.f, 0.f, 0.f, 0.f);
            }
        }

        // ---- stage 3: @W2 + b2, hsw; gate from registers ----
        mm_stage<4>(As, W2s, acc, tr, tc);
        #pragma unroll
        for (int i = 0; i < 4; i++) {
            int gr = t * 64 + tr * 4 + i;
            float2 v0 = unpack2(acc[i][0]), v1 = unpack2(acc[i][1]);
            float vv[4] = {v0.x, v0.y, v1.x, v1.y};
            float4 o;
            float* op = (float*)&o;
            #pragma unroll
            for (int j = 0; j < 4; j++) op[j] = hsw(vv[j] + b2c[j]);
            if (!LAST) {
                float p = op[0] * wgc[0] + op[1] * wgc[1] + op[2] * wgc[2] + op[3] * wgc[3];
                #pragma unroll
                for (int o2 = 16; o2; o2 >>= 1) p += __shfl_xor_sync(0xffffffffu, p, o2);
                if (tc == 0 && gr < nrows) gate[gr] = p + bg0;
            }
            if (gr < nrows) ((float4*)(hout + (size_t)gr * DD))[tc] = o;
        }
        __syncthreads();
        if (tn < ntiles) {
            float4* As4 = (float4*)As;
            #pragma unroll
            for (int it = 0; it < 4; it++) As4[it * 512 + tid] = pf[it];
        }
    }
}

// ---------------- head: z = hsw(h@Wp1+bp1); logits = z@Wp2+bp2; log_softmax ----
__global__ void __launch_bounds__(512)
head2_kernel(const float* __restrict__ h, const float* __restrict__ Wp1,
             const float* __restrict__ bp1, const float* __restrict__ Wp2,
             const float* __restrict__ bp2, float* __restrict__ out, int n) {
    extern __shared__ float sm[];
    float* Wp1s = sm;                        // 16384 f
    float* As   = sm + 16384;                // 128x128 f
    unsigned long long* wsh = (unsigned long long*)(sm + 32768);  // 128*20 u64
    const int tid = threadIdx.x;
    const int tc  = tid & 31;
    const int tr  = tid >> 5;
    const int r0  = blockIdx.x * 128;

    {   // stage Wp1
        const float4* w = (const float4*)Wp1;
        float4* s = (float4*)Wp1s;
        #pragma unroll
        for (int it = 0; it < 8; it++) s[it * 512 + tid] = w[it * 512 + tid];
    }
    for (int idx = tid; idx < DD * 20; idx += 512) {
        int k = idx / 20, j = idx % 20;
        wsh[idx] = pack2(Wp2[k * CC + 2 * j], Wp2[k * CC + 2 * j + 1]);
    }
    {   // stage A tile (128 rows)
        float4* As4 = (float4*)As;
        #pragma unroll
        for (int it = 0; it < 8; it++) {
            int idx = it * 512 + tid;
            int r = idx >> 5, c4 = idx & 31;
            float4 v = make_float4(0.f, 0.f, 0.f, 0.f);
            if (r0 + r < n) v = ((const float4*)(h + (size_t)(r0 + r) * DD))[c4];
            As4[idx] = v;
        }
    }
    __syncthreads();

    // stage 1: z = hsw(h @ Wp1 + bp1)
    unsigned long long acc1[8][2];
    mm_stage<8>(As, Wp1s, acc1, tr, tc);
    const int c0 = tc * 4;
    float bc[4];
    #pragma unroll
    for (int j = 0; j < 4; j++) bc[j] = bp1[c0 + j];
    float zz[8][4];
    #pragma unroll
    for (int i = 0; i < 8; i++) {
        float2 v0 = unpack2(acc1[i][0]), v1 = unpack2(acc1[i][1]);
        float vv[4] = {v0.x, v0.y, v1.x, v1.y};
        #pragma unroll
        for (int j = 0; j < 4; j++) zz[i][j] = hsw(vv[j] + bc[j]);
    }
    __syncthreads();
    #pragma unroll
    for (int i = 0; i < 8; i++)
        ((float4*)(As + (tr * 8 + i) * DD))[tc] = make_float4(zz[i][0], zz[i][1], zz[i][2], zz[i][3]);
    __syncthreads();

    // stage 2: per-row logits + log_softmax (4 threads per row, 10 classes each)
    const int rl = tid >> 2;     // 0..127
    const int q  = tid & 3;      // col group: classes q*10 .. q*10+9
    unsigned long long acc[5];
    #pragma unroll
    for (int j = 0; j < 5; j++)
        acc[j] = pack2(bp2[q * 10 + 2 * j], bp2[q * 10 + 2 * j + 1]);
    const float* ar = As + rl * DD;
    #pragma unroll 4
    for (int k = 0; k < DD; k++) {
        float a = ar[k];
        unsigned long long ad = pack2(a, a);
        const unsigned long long* wr = wsh + k * 20 + q * 5;
        #pragma unroll
        for (int j = 0; j < 5; j++) acc[j] = ffma2(ad, wr[j], acc[j]);
    }
    float vals[10];
    #pragma unroll
    for (int j = 0; j < 5; j++) {
        float2 p = unpack2(acc[j]);
        vals[2 * j] = p.x;
        vals[2 * j + 1] = p.y;
    }
    float mx = vals[0];
    #pragma unroll
    for (int c = 1; c < 10; c++) mx = fmaxf(mx, vals[c]);
    mx = fmaxf(mx, __shfl_xor_sync(0xffffffffu, mx, 1));
    mx = fmaxf(mx, __shfl_xor_sync(0xffffffffu, mx, 2));
    float s = 0.f;
    #pragma unroll
    for (int c = 0; c < 10; c++) s += __expf(vals[c] - mx);
    s += __shfl_xor_sync(0xffffffffu, s, 1);
    s += __shfl_xor_sync(0xffffffffu, s, 2);
    float lse = mx + logf(s);
    int gr = r0 + rl;
    if (gr < n) {
        #pragma unroll
        for (int c = 0; c < 10; c++) out[(size_t)gr * CC + q * 10 + c] = vals[c] - lse;
    }
}

// ---------------- launch orchestration ----------------
extern "C" void kernel_launch(void* const* d_in, const int* in_sizes, int n_in,
                              void* d_out, int out_size) {
    const float* x   = (const float*)d_in[0];
    const int*   src = (const int*)d_in[1];
    const int*   dst = (const int*)d_in[2];
    const float* Wg  = (const float*)d_in[3];
    const float* bg  = (const float*)d_in[4];
    const float* Wt  = (const float*)d_in[5];
    const float* bt  = (const float*)d_in[6];
    const float* W1  = (const float*)d_in[7];
    const float* b1  = (const float*)d_in[8];
    const float* bng = (const float*)d_in[9];
    const float* bnb = (const float*)d_in[10];
    const float* bnm = (const float*)d_in[11];
    const float* bnv = (const float*)d_in[12];
    const float* W2  = (const float*)d_in[13];
    const float* b2  = (const float*)d_in[14];
    const float* Wp1 = (const float*)d_in[15];
    const float* bp1 = (const float*)d_in[16];
    const float* Wp2 = (const float*)d_in[17];
    const float* bp2 = (const float*)d_in[18];
    float* out = (float*)d_out;

    const int n = in_sizes[0] / DD;
    const int e = in_sizes[1];

    float *ph, *pagg, *pg;
    int *prow, *pcur, *psrc;
    cudaGetSymbolAddress((void**)&ph,   g_h);
    cudaGetSymbolAddress((void**)&pagg, g_agg);
    cudaGetSymbolAddress((void**)&pg,   g_gate);
    cudaGetSymbolAddress((void**)&prow, g_rowptr);
    cudaGetSymbolAddress((void**)&pcur, g_cursor);
    cudaGetSymbolAddress((void**)&psrc, g_srcs);

    const int CHAIN_SMEM = (3 * DD * DD + 64 * DD) * (int)sizeof(float);     // 224 KB
    const int HEAD_SMEM  = 2 * DD * DD * (int)sizeof(float)
                         + DD * 20 * (int)sizeof(unsigned long long);        // 148 KB
    cudaFuncSetAttribute(chain3<0>, cudaFuncAttributeMaxDynamicSharedMemorySize, CHAIN_SMEM);
    cudaFuncSetAttribute(chain3<1>, cudaFuncAttributeMaxDynamicSharedMemorySize, CHAIN_SMEM);
    cudaFuncSetAttribute(head2_kernel, cudaFuncAttributeMaxDynamicSharedMemorySize, HEAD_SMEM);

    // CSR build + layer-0 gate
    cudaMemsetAsync(pcur, 0, n * sizeof(int));
    count_ext_kernel<<<(e + n + 255) / 256, 256>>>(dst, pcur, e, n);   // launch 0
    scan_kernel<<<1, 1024>>>(pcur, prow, n);                           // launch 1
    const int SB = (e + n + 255) / 256;
    const int GB = (n + 7) / 8;
    scatter_gate_kernel<<<SB + GB, 256>>>(src, dst, pcur, psrc,
                                          x, Wg, bg, pg, e, n, SB);    // launch 2

    const int wblocks = (n * 32 + 255) / 256;
    const int PERS = 148;

    for (int i = 0; i < LL; i++) {
        const float* hin = (i == 0) ? x : ph;
        edge_agg_kernel<<<wblocks, 256>>>(prow, psrc, pg, hin, pagg, n);   // layer0 = launch 3
        if (i < LL - 1) {
            chain3<0><<<PERS, 512, CHAIN_SMEM>>>(
                pagg,
                Wt + (size_t)i * DD * DD, bt + (size_t)i * DD,
                W1 + (size_t)i * DD * DD, b1 + (size_t)i * DD,
                bng + (size_t)i * DD, bnb + (size_t)i * DD,
                bnm + (size_t)i * DD, bnv + (size_t)i * DD,
                W2 + (size_t)i * DD * DD, b2 + (size_t)i * DD,
                Wg + (size_t)(i + 1) * DD, bg + (i + 1),
                ph, pg, n);
        } else {
            chain3<1><<<PERS, 512, CHAIN_SMEM>>>(
                pagg,
                Wt + (size_t)i * DD * DD, bt + (size_t)i * DD,
                W1 + (size_t)i * DD * DD, b1 + (size_t)i * DD,
                bng + (size_t)i * DD, bnb + (size_t)i * DD,
                bnm + (size_t)i * DD, bnv + (size_t)i * DD,
                W2 + (size_t)i * DD * DD, b2 + (size_t)i * DD,
                nullptr, nullptr,
                ph, nullptr, n);
        }
    }
    head2_kernel<<<(n + 127) / 128, 512, HEAD_SMEM>>>(ph, Wp1, bp1, Wp2, bp2, out, n);
}

// round 9
// speedup vs baseline: 1.4690x; 1.3808x over previous
#include <cuda_runtime.h>
#include <cuda_bf16.h>
#include <cstdint>

#define NN 50000
#define DD 128
#define EE 600000
#define CC 40
#define LL 4

// ---------------- scratch (static device globals; no allocation) ----------------
__device__ __align__(16) float g_h  [NN * DD];
__device__ __align__(16) float g_agg[NN * DD];
__device__ __align__(16) float g_gate[NN];
__device__ __align__(16) int   g_rowptr[NN + 4];
__device__ __align__(16) int   g_cursor[NN];
__device__ __align__(16) int   g_srcs[EE + NN];

// ---------------- fp32 packed-FMA helpers (head kernel) ----------------------
__device__ __forceinline__ unsigned long long ffma2(unsigned long long a,
                                                    unsigned long long b,
                                                    unsigned long long c) {
    unsigned long long d;
    asm("fma.rn.f32x2 %0, %1, %2, %3;" : "=l"(d) : "l"(a), "l"(b), "l"(c));
    return d;
}
__device__ __forceinline__ unsigned long long pack2(float x, float y) {
    unsigned long long r;
    asm("mov.b64 %0, {%1, %2};" : "=l"(r) : "f"(x), "f"(y));
    return r;
}
__device__ __forceinline__ float2 unpack2(unsigned long long v) {
    float2 f;
    asm("mov.b64 {%0, %1}, %2;" : "=f"(f.x), "=f"(f.y) : "l"(v));
    return f;
}
__device__ __forceinline__ float hsw(float x) {
    return x * fminf(fmaxf(x + 3.f, 0.f), 6.f) * (1.f / 6.f);
}
__device__ __forceinline__ uint32_t smem_u32(const void* p) {
    uint32_t a;
    asm("{ .reg .u64 t; cvta.to.shared.u64 t, %1; cvt.u32.u64 %0, t; }" : "=r"(a) : "l"(p));
    return a;
}

// split fp32 pair into bf16x2 hi (returned) and bf16x2 lo (out param).
// memory/lane order: low half = x0, high half = x1.
__device__ __forceinline__ uint32_t split_pair(float x0, float x1, uint32_t& lo_pair) {
    uint32_t hi;
    asm("cvt.rn.bf16x2.f32 %0, %1, %2;" : "=r"(hi) : "f"(x1), "f"(x0));
    float h0 = __uint_as_float(hi << 16);
    float h1 = __uint_as_float(hi & 0xffff0000u);
    float l0 = x0 - h0, l1 = x1 - h1;
    asm("cvt.rn.bf16x2.f32 %0, %1, %2;" : "=r"(lo_pair) : "f"(l1), "f"(l0));
    return hi;
}

#define LDM4(r0, r1, r2, r3, addr) \
    asm volatile("ldmatrix.sync.aligned.m8n8.x4.shared.b16 {%0,%1,%2,%3}, [%4];" \
                 : "=r"(r0), "=r"(r1), "=r"(r2), "=r"(r3) : "r"(addr))

#define MMA16816(d, a0, a1, a2, a3, b0, b1) \
    asm("mma.sync.aligned.m16n8k16.row.col.f32.bf16.bf16.f32 " \
        "{%0,%1,%2,%3}, {%4,%5,%6,%7}, {%8,%9}, {%0,%1,%2,%3};" \
        : "+f"(d[0]), "+f"(d[1]), "+f"(d[2]), "+f"(d[3]) \
        : "r"(a0), "r"(a1), "r"(a2), "r"(a3), "r"(b0), "r"(b1))

// ---------------- CSR build ----------------
__global__ void count_ext_kernel(const int* __restrict__ dst, int* __restrict__ cursor,
                                 int e, int n) {
    int i = blockIdx.x * blockDim.x + threadIdx.x;
    if (i >= e + n) return;
    int d = (i < e) ? dst[i] : (i - e);
    atomicAdd(&cursor[d], 1);
}

__global__ void scan_kernel(int* __restrict__ cursor, int* __restrict__ rowptr, int n) {
    __shared__ int wsum[32];
    const int lane = threadIdx.x & 31;
    const int wid  = threadIdx.x >> 5;
    int carry = 0;
    for (int base = 0; base < n; base += 4096) {
        int idx = base + threadIdx.x * 4;
        int4 v = make_int4(0, 0, 0, 0);
        if (idx < n) v = *(const int4*)(cursor + idx);
        int t = v.x + v.y + v.z + v.w;
        int x = t;
        #pragma unroll
        for (int o = 1; o < 32; o <<= 1) {
            int y = __shfl_up_sync(0xffffffffu, x, o);
            if (lane >= o) x += y;
        }
        if (lane == 31) wsum[wid] = x;
        __syncthreads();
        if (wid == 0) {
            int s = wsum[lane];
            #pragma unroll
            for (int o = 1; o < 32; o <<= 1) {
                int y = __shfl_up_sync(0xffffffffu, s, o);
                if (lane >= o) s += y;
            }
            wsum[lane] = s;
        }
        __syncthreads();
        int excl = carry + (wid ? wsum[wid - 1] : 0) + x - t;
        if (idx < n) {
            int4 r;
            r.x = excl;
            r.y = excl + v.x;
            r.z = r.y + v.y;
            r.w = r.z + v.z;
            *(int4*)(rowptr + idx) = r;
            *(int4*)(cursor + idx) = r;
        }
        carry += wsum[31];
        __syncthreads();
    }
    if (threadIdx.x == 0) rowptr[n] = carry;
}

__global__ void __launch_bounds__(256)
scatter_gate_kernel(const int* __restrict__ src, const int* __restrict__ dst,
                    int* __restrict__ cursor, int* __restrict__ srcs,
                    const float* __restrict__ x, const float* __restrict__ Wg0,
                    const float* __restrict__ bg0, float* __restrict__ gate,
                    int e, int n, int SB) {
    if ((int)blockIdx.x < SB) {
        int i = blockIdx.x * 256 + threadIdx.x;
        if (i >= e + n) return;
        int d, s;
        if (i < e) { d = dst[i]; s = src[i]; }
        else       { d = i - e;  s = i - e;  }
        int p = atomicAdd(&cursor[d], 1);
        srcs[p] = s;
    } else {
        int bid2 = blockIdx.x - SB;
        int row  = bid2 * 8 + (threadIdx.x >> 5);
        int lane = threadIdx.x & 31;
        if (row >= n) return;
        float4 a = ((const float4*)(x + (size_t)row * DD))[lane];
        float4 b = ((const float4*)Wg0)[lane];
        float s  = a.x * b.x + a.y * b.y + a.z * b.z + a.w * b.w;
        #pragma unroll
        for (int o = 16; o; o >>= 1) s += __shfl_xor_sync(0xffffffffu, s, o);
        if (lane == 0) gate[row] = s + bg0[0];
    }
}

// ---------------- fused softmax-attention aggregation (warp per dst node) -----
__global__ void __launch_bounds__(256)
edge_agg_kernel(const int* __restrict__ rowptr, const int* __restrict__ srcs,
                const float* __restrict__ g, const float* __restrict__ h,
                float* __restrict__ agg, int n) {
    int gt   = blockIdx.x * blockDim.x + threadIdx.x;
    int w    = gt >> 5;
    int lane = gt & 31;
    if (w >= n) return;
    int beg = rowptr[w];
    int end = rowptr[w + 1];

    float m = -3.4e38f, s = 0.f;
    for (int j0 = beg; j0 < end; j0 += 32) {
        int  j  = j0 + lane;
        bool ok = (j < end);
        float gi = ok ? g[srcs[j]] : -3.4e38f;
        float mn = fmaxf(m, gi);
        s = s * __expf(m - mn) + (ok ? __expf(gi - mn) : 0.f);
        m = mn;
    }
    #pragma unroll
    for (int o = 16; o; o >>= 1) {
        float om = __shfl_xor_sync(0xffffffffu, m, o);
        float os = __shfl_xor_sync(0xffffffffu, s, o);
        float mn = fmaxf(m, om);
        s = s * __expf(m - mn) + os * __expf(om - mn);
        m = mn;
    }
    float inv = 1.f / s;

    float4 acc0 = make_float4(0.f, 0.f, 0.f, 0.f);
    float4 acc1 = make_float4(0.f, 0.f, 0.f, 0.f);
    for (int j0 = beg; j0 < end; j0 += 32) {
        int  j  = j0 + lane;
        bool ok = (j < end);
        int   sj  = ok ? srcs[j] : 0;
        float wgt = ok ? __expf(g[sj] - m) * inv : 0.f;
        int cnt = min(32, end - j0);
        int jj = 0;
        for (; jj + 1 < cnt; jj += 2) {
            float w0 = __shfl_sync(0xffffffffu, wgt, jj);
            float w1 = __shfl_sync(0xffffffffu, wgt, jj + 1);
            int   s0 = __shfl_sync(0xffffffffu, sj, jj);
            int   s1 = __shfl_sync(0xffffffffu, sj, jj + 1);
            float4 v0 = ((const float4*)(h + (size_t)s0 * DD))[lane];
            float4 v1 = ((const float4*)(h + (size_t)s1 * DD))[lane];
            acc0.x = fmaf(w0, v0.x, acc0.x); acc1.x = fmaf(w1, v1.x, acc1.x);
            acc0.y = fmaf(w0, v0.y, acc0.y); acc1.y = fmaf(w1, v1.y, acc1.y);
            acc0.z = fmaf(w0, v0.z, acc0.z); acc1.z = fmaf(w1, v1.z, acc1.z);
            acc0.w = fmaf(w0, v0.w, acc0.w); acc1.w = fmaf(w1, v1.w, acc1.w);
        }
        if (jj < cnt) {
            float w0 = __shfl_sync(0xffffffffu, wgt, jj);
            int   s0 = __shfl_sync(0xffffffffu, sj, jj);
            float4 v0 = ((const float4*)(h + (size_t)s0 * DD))[lane];
            acc0.x = fmaf(w0, v0.x, acc0.x);
            acc0.y = fmaf(w0, v0.y, acc0.y);
            acc0.z = fmaf(w0, v0.z, acc0.z);
            acc0.w = fmaf(w0, v0.w, acc0.w);
        }
    }
    acc0.x += acc1.x; acc0.y += acc1.y; acc0.z += acc1.z; acc0.w += acc1.w;
    ((float4*)(agg + (size_t)w * DD))[lane] = acc0;
}

// =====================================================================
// HMMA fused layer chain (persistent, 256 threads, 1 block/SM).
// Weights: 3 stages x (hi,lo) bf16, transposed [n][k], swizzled, in smem.
// A & inter-stage activations: bf16 hi/lo pairs in smem (32-row tiles).
// 3-product split: x.w = xh.wh + xl.wh + xh.wl  (drop xl.wl ~ 2^-18).
// stage0: t  = A @ Wt          (bt folded into b1')
// stage1: z  = hsw(BN(t @ W1 + b1'))  with b1' = bt@W1 + b1
// stage2: h  = hsw(z @ W2 + b2); (!LAST) gate = h . WgN + bgN
// =====================================================================
#define W_BYTES   32768
#define SM_W      0
#define SM_A      (6 * W_BYTES)        /* 196608 */
#define SM_CONST  (SM_A + 16384)       /* 212992 */
#define SM_GATEP  (SM_CONST + 2560)    /* 215552 */
#define CHAIN_SMEM (SM_GATEP + 512)    /* 216064 */

template <int LAST>
__global__ void __launch_bounds__(256)
chain3_mma(const float* __restrict__ A,
           const float* __restrict__ Wt,  const float* __restrict__ bt,
           const float* __restrict__ W1,  const float* __restrict__ b1,
           const float* __restrict__ bng, const float* __restrict__ bnb,
           const float* __restrict__ bnm, const float* __restrict__ bnv,
           const float* __restrict__ W2,  const float* __restrict__ b2,
           const float* __restrict__ WgN, const float* __restrict__ bgN,
           float* __restrict__ hout, float* __restrict__ gate, int nrows) {
    extern __shared__ char smem[];
    const uint32_t sb = smem_u32(smem);
    float* cst = (float*)(smem + SM_CONST);   // b1' | scale | shift | b2 | wg
    float* gpp = (float*)(smem + SM_GATEP);   // 32 rows x 4 colblocks
    const int tid  = threadIdx.x;
    const int wid  = tid >> 5;
    const int lane = tid & 31;
    const int mt = wid & 1;          // row block of 16
    const int nb = wid >> 1;         // col block of 32
    const int g  = lane >> 2, tg = lane & 3;
    const int lq = lane >> 3, lr = lane & 7;

    // ---- stage weights: fp32 -> (hi,lo) bf16, transpose to [n][k], swizzle ----
    const float* WS[3] = {Wt, W1, W2};
    #pragma unroll
    for (int m = 0; m < 3; m++) {
        char* hi_s = smem + SM_W + m * 2 * W_BYTES;
        char* lo_s = hi_s + W_BYTES;
        const float* W = WS[m];
        for (int i = tid; i < DD * DD; i += 256) {
            int k = i >> 7, n = i & 127;
            float w = W[i];
            __nv_bfloat16 hb = __float2bfloat16(w);
            __nv_bfloat16 lb = __float2bfloat16(w - __bfloat162float(hb));
            int off = n * 256 + (((k >> 3) ^ (n & 7)) << 4) + (k & 7) * 2;
            *(__nv_bfloat16*)(hi_s + off) = hb;
            *(__nv_bfloat16*)(lo_s + off) = lb;
        }
    }
    // ---- epilogue constants; fold bt: b1' = bt @ W1 + b1 ----
    if (tid < 128) {
        float a = b1[tid];
        for (int k = 0; k < 128; k++) a = fmaf(bt[k], W1[k * 128 + tid], a);
        cst[tid] = a;
        float sv = bng[tid] * rsqrtf(bnv[tid] + 1e-5f);
        cst[128 + tid] = sv;
        cst[256 + tid] = bnb[tid] - bnm[tid] * sv;
        cst[384 + tid] = b2[tid];
        cst[512 + tid] = LAST ? 0.f : WgN[tid];
    }
    __syncthreads();
    const float bgv = LAST ? 0.f : bgN[0];

    const uint32_t As_hi = sb + SM_A;
    const uint32_t As_lo = As_hi + 8192;
    // ldmatrix per-lane row bases (x4 quadrant mapping)
    const int a_row = mt * 16 + lr + ((lq & 1) << 3);
    const int a_kh  = lq >> 1;
    const int b_row = nb * 32 + lr + ((lq >> 1) << 3);
    const int b_kh  = lq & 1;
    const uint32_t aRowHi = As_hi + a_row * 256;
    const uint32_t aRowLo = As_lo + a_row * 256;
    const int r0l = mt * 16 + g;      // epilogue rows r0l, r0l+8

    const int ntiles = (nrows + 31) >> 5;
    for (int t = blockIdx.x; t < ntiles; t += gridDim.x) {
        // ---- load A tile fp32 -> split -> smem bf16 hi/lo ----
        #pragma unroll
        for (int it = 0; it < 4; it++) {
            int s = it * 256 + tid;
            int r = s >> 5, c4 = s & 31;
            int grow = t * 32 + r;
            float4 f = make_float4(0.f, 0.f, 0.f, 0.f);
            if (grow < nrows) f = ((const float4*)(A + (size_t)grow * DD))[c4];
            uint32_t l01, l23;
            uint32_t h01 = split_pair(f.x, f.y, l01);
            uint32_t h23 = split_pair(f.z, f.w, l23);
            uint32_t off = (uint32_t)r * 256
                         + ((uint32_t)((c4 >> 1) ^ (r & 7)) << 4) + (c4 & 1) * 8;
            *(uint2*)(smem + SM_A + off)        = make_uint2(h01, h23);
            *(uint2*)(smem + SM_A + 8192 + off) = make_uint2(l01, l23);
        }
        __syncthreads();

        #pragma unroll
        for (int st = 0; st < 3; st++) {
            const uint32_t wHi = sb + SM_W + st * 2 * W_BYTES;
            const uint32_t wLo = wHi + W_BYTES;
            const uint32_t bRowHi = wHi + b_row * 256;
            const uint32_t bRowLo = wLo + b_row * 256;
            float acc[4][4];
            #pragma unroll
            for (int i = 0; i < 4; i++) {
                acc[i][0] = 0.f; acc[i][1] = 0.f; acc[i][2] = 0.f; acc[i][3] = 0.f;
            }
            #pragma unroll
            for (int kk = 0; kk < 8; kk++) {
                uint32_t ca = (uint32_t)(((2 * kk + a_kh) ^ lr) << 4);
                uint32_t cb = (uint32_t)(((2 * kk + b_kh) ^ lr) << 4);
                uint32_t ah0, ah1, ah2, ah3, al0, al1, al2, al3;
                LDM4(ah0, ah1, ah2, ah3, aRowHi + ca);
                LDM4(al0, al1, al2, al3, aRowLo + ca);
                uint32_t bh0, bh1, bh2, bh3, bh4, bh5, bh6, bh7;
                LDM4(bh0, bh1, bh2, bh3, bRowHi + cb);
                LDM4(bh4, bh5, bh6, bh7, bRowHi + 4096 + cb);
                uint32_t bl0, bl1, bl2, bl3, bl4, bl5, bl6, bl7;
                LDM4(bl0, bl1, bl2, bl3, bRowLo + cb);
                LDM4(bl4, bl5, bl6, bl7, bRowLo + 4096 + cb);
                MMA16816(acc[0], ah0, ah1, ah2, ah3, bh0, bh1);
                MMA16816(acc[1], ah0, ah1, ah2, ah3, bh2, bh3);
                MMA16816(acc[2], ah0, ah1, ah2, ah3, bh4, bh5);
                MMA16816(acc[3], ah0, ah1, ah2, ah3, bh6, bh7);
                MMA16816(acc[0], al0, al1, al2, al3, bh0, bh1);
                MMA16816(acc[1], al0, al1, al2, al3, bh2, bh3);
                MMA16816(acc[2], al0, al1, al2, al3, bh4, bh5);
                MMA16816(acc[3], al0, al1, al2, al3, bh6, bh7);
                MMA16816(acc[0], ah0, ah1, ah2, ah3, bl0, bl1);
                MMA16816(acc[1], ah0, ah1, ah2, ah3, bl2, bl3);
                MMA16816(acc[2], ah0, ah1, ah2, ah3, bl4, bl5);
                MMA16816(acc[3], ah0, ah1, ah2, ah3, bl6, bl7);
            }
            __syncthreads();   // all warps done reading As before overwrite

            if (st < 2) {
                #pragma unroll
                for (int tt = 0; tt < 4; tt++) {
                    int ct = nb * 32 + tt * 8;
                    int c0 = ct + 2 * tg, c1 = c0 + 1;
                    float v0 = acc[tt][0], v1 = acc[tt][1];
                    float v2 = acc[tt][2], v3 = acc[tt][3];
                    if (st == 1) {
                        v0 = hsw((v0 + cst[c0]) * cst[128 + c0] + cst[256 + c0]);
                        v1 = hsw((v1 + cst[c1]) * cst[128 + c1] + cst[256 + c1]);
                        v2 = hsw((v2 + cst[c0]) * cst[128 + c0] + cst[256 + c0]);
                        v3 = hsw((v3 + cst[c1]) * cst[128 + c1] + cst[256 + c1]);
                    }
                    uint32_t lo01, lo23;
                    uint32_t h01 = split_pair(v0, v1, lo01);
                    uint32_t h23 = split_pair(v2, v3, lo23);
                    uint32_t chunk = (uint32_t)(((ct >> 3) ^ (r0l & 7)) << 4) + 4 * tg;
                    uint32_t off0 = (uint32_t)r0l * 256 + chunk;
                    uint32_t off1 = (uint32_t)(r0l + 8) * 256 + chunk;
                    *(uint32_t*)(smem + SM_A + off0)        = h01;
                    *(uint32_t*)(smem + SM_A + off1)        = h23;
                    *(uint32_t*)(smem + SM_A + 8192 + off0) = lo01;
                    *(uint32_t*)(smem + SM_A + 8192 + off1) = lo23;
                }
                __syncthreads();
            } else {
                int gr0 = t * 32 + r0l, gr1 = gr0 + 8;
                float p0 = 0.f, p1 = 0.f;
                #pragma unroll
                for (int tt = 0; tt < 4; tt++) {
                    int ct = nb * 32 + tt * 8;
                    int c0 = ct + 2 * tg, c1 = c0 + 1;
                    float q0 = hsw(acc[tt][0] + cst[384 + c0]);
                    float q1 = hsw(acc[tt][1] + cst[384 + c1]);
                    float q2 = hsw(acc[tt][2] + cst[384 + c0]);
                    float q3 = hsw(acc[tt][3] + cst[384 + c1]);
                    if (!LAST) {
                        p0 = fmaf(q0, cst[512 + c0], fmaf(q1, cst[512 + c1], p0));
                        p1 = fmaf(q2, cst[512 + c0], fmaf(q3, cst[512 + c1], p1));
                    }
                    if (gr0 < nrows)
                        *(float2*)(hout + (size_t)gr0 * DD + c0) = make_float2(q0, q1);
                    if (gr1 < nrows)
                        *(float2*)(hout + (size_t)gr1 * DD + c0) = make_float2(q2, q3);
                }
                if (!LAST) {
                    p0 += __shfl_xor_sync(0xffffffffu, p0, 1);
                    p0 += __shfl_xor_sync(0xffffffffu, p0, 2);
                    p1 += __shfl_xor_sync(0xffffffffu, p1, 1);
                    p1 += __shfl_xor_sync(0xffffffffu, p1, 2);
                    if (tg == 0) {
                        gpp[r0l * 4 + nb]       = p0;
                        gpp[(r0l + 8) * 4 + nb] = p1;
                    }
                }
            }
        }
        if (!LAST) {
            __syncthreads();
            if (tid < 32) {
                int gr = t * 32 + tid;
                if (gr < nrows)
                    gate[gr] = gpp[tid * 4] + gpp[tid * 4 + 1]
                             + gpp[tid * 4 + 2] + gpp[tid * 4 + 3] + bgv;
            }
        }
        __syncthreads();
    }
}

// ---------------- FFMA tile MMA for head ----------------
template <int R>
__device__ __forceinline__ void mm_stage(const float* __restrict__ As,
                                         const float* __restrict__ Ws,
                                         unsigned long long acc[R][2],
                                         int tr, int tc) {
    #pragma unroll
    for (int i = 0; i < R; i++) { acc[i][0] = 0ull; acc[i][1] = 0ull; }
    const float4*     Arow = (const float4*)(As + tr * R * DD);
    const ulonglong2* Wsu  = ((const ulonglong2*)Ws) + tc;
    #pragma unroll 2
    for (int k4 = 0; k4 < 32; k4++) {
        float4 a[R];
        #pragma unroll
        for (int i = 0; i < R; i++) a[i] = Arow[i * 32 + k4];
        #pragma unroll
        for (int kk = 0; kk < 4; kk++) {
            ulonglong2 wp = Wsu[(k4 * 4 + kk) * 32];
            #pragma unroll
            for (int i = 0; i < R; i++) {
                float av = (kk == 0) ? a[i].x : (kk == 1) ? a[i].y : (kk == 2) ? a[i].z : a[i].w;
                unsigned long long ad = pack2(av, av);
                acc[i][0] = ffma2(ad, wp.x, acc[i][0]);
                acc[i][1] = ffma2(ad, wp.y, acc[i][1]);
            }
        }
    }
}

// ---------------- head: z = hsw(h@Wp1+bp1); logits=z@Wp2+bp2; log_softmax ----
__global__ void __launch_bounds__(512)
head2_kernel(const float* __restrict__ h, const float* __restrict__ Wp1,
             const float* __restrict__ bp1, const float* __restrict__ Wp2,
             const float* __restrict__ bp2, float* __restrict__ out, int n) {
    extern __shared__ float sm[];
    float* Wp1s = sm;
    float* As   = sm + 16384;
    unsigned long long* wsh = (unsigned long long*)(sm + 32768);
    const int tid = threadIdx.x;
    const int tc  = tid & 31;
    const int tr  = tid >> 5;
    const int r0  = blockIdx.x * 128;

    {
        const float4* w = (const float4*)Wp1;
        float4* s = (float4*)Wp1s;
        #pragma unroll
        for (int it = 0; it < 8; it++) s[it * 512 + tid] = w[it * 512 + tid];
    }
    for (int idx = tid; idx < DD * 20; idx += 512) {
        int k = idx / 20, j = idx % 20;
        wsh[idx] = pack2(Wp2[k * CC + 2 * j], Wp2[k * CC + 2 * j + 1]);
    }
    {
        float4* As4 = (float4*)As;
        #pragma unroll
        for (int it = 0; it < 8; it++) {
            int idx = it * 512 + tid;
            int r = idx >> 5, c4 = idx & 31;
            float4 v = make_float4(0.f, 0.f, 0.f, 0.f);
            if (r0 + r < n) v = ((const float4*)(h + (size_t)(r0 + r) * DD))[c4];
            As4[idx] = v;
        }
    }
    __syncthreads();

    unsigned long long acc1[8][2];
    mm_stage<8>(As, Wp1s, acc1, tr, tc);
    const int c0 = tc * 4;
    float bc[4];
    #pragma unroll
    for (int j = 0; j < 4; j++) bc[j] = bp1[c0 + j];
    float zz[8][4];
    #pragma unroll
    for (int i = 0; i < 8; i++) {
        float2 v0 = unpack2(acc1[i][0]), v1 = unpack2(acc1[i][1]);
        float vv[4] = {v0.x, v0.y, v1.x, v1.y};
        #pragma unroll
        for (int j = 0; j < 4; j++) zz[i][j] = hsw(vv[j] + bc[j]);
    }
    __syncthreads();
    #pragma unroll
    for (int i = 0; i < 8; i++)
        ((float4*)(As + (tr * 8 + i) * DD))[tc] = make_float4(zz[i][0], zz[i][1], zz[i][2], zz[i][3]);
    __syncthreads();

    const int rl = tid >> 2;
    const int q  = tid & 3;
    unsigned long long acc[5];
    #pragma unroll
    for (int j = 0; j < 5; j++)
        acc[j] = pack2(bp2[q * 10 + 2 * j], bp2[q * 10 + 2 * j + 1]);
    const float* ar = As + rl * DD;
    #pragma unroll 4
    for (int k = 0; k < DD; k++) {
        float a = ar[k];
        unsigned long long ad = pack2(a, a);
        const unsigned long long* wr = wsh + k * 20 + q * 5;
        #pragma unroll
        for (int j = 0; j < 5; j++) acc[j] = ffma2(ad, wr[j], acc[j]);
    }
    float vals[10];
    #pragma unroll
    for (int j = 0; j < 5; j++) {
        float2 p = unpack2(acc[j]);
        vals[2 * j] = p.x;
        vals[2 * j + 1] = p.y;
    }
    float mx = vals[0];
    #pragma unroll
    for (int c = 1; c < 10; c++) mx = fmaxf(mx, vals[c]);
    mx = fmaxf(mx, __shfl_xor_sync(0xffffffffu, mx, 1));
    mx = fmaxf(mx, __shfl_xor_sync(0xffffffffu, mx, 2));
    float s = 0.f;
    #pragma unroll
    for (int c = 0; c < 10; c++) s += __expf(vals[c] - mx);
    s += __shfl_xor_sync(0xffffffffu, s, 1);
    s += __shfl_xor_sync(0xffffffffu, s, 2);
    float lse = mx + logf(s);
    int gr = r0 + rl;
    if (gr < n) {
        #pragma unroll
        for (int c = 0; c < 10; c++) out[(size_t)gr * CC + q * 10 + c] = vals[c] - lse;
    }
}

// ---------------- launch orchestration ----------------
extern "C" void kernel_launch(void* const* d_in, const int* in_sizes, int n_in,
                              void* d_out, int out_size) {
    const float* x   = (const float*)d_in[0];
    const int*   src = (const int*)d_in[1];
    const int*   dst = (const int*)d_in[2];
    const float* Wg  = (const float*)d_in[3];
    const float* bg  = (const float*)d_in[4];
    const float* Wt  = (const float*)d_in[5];
    const float* bt  = (const float*)d_in[6];
    const float* W1  = (const float*)d_in[7];
    const float* b1  = (const float*)d_in[8];
    const float* bng = (const float*)d_in[9];
    const float* bnb = (const float*)d_in[10];
    const float* bnm = (const float*)d_in[11];
    const float* bnv = (const float*)d_in[12];
    const float* W2  = (const float*)d_in[13];
    const float* b2  = (const float*)d_in[14];
    const float* Wp1 = (const float*)d_in[15];
    const float* bp1 = (const float*)d_in[16];
    const float* Wp2 = (const float*)d_in[17];
    const float* bp2 = (const float*)d_in[18];
    float* out = (float*)d_out;

    const int n = in_sizes[0] / DD;
    const int e = in_sizes[1];

    float *ph, *pagg, *pg;
    int *prow, *pcur, *psrc;
    cudaGetSymbolAddress((void**)&ph,   g_h);
    cudaGetSymbolAddress((void**)&pagg, g_agg);
    cudaGetSymbolAddress((void**)&pg,   g_gate);
    cudaGetSymbolAddress((void**)&prow, g_rowptr);
    cudaGetSymbolAddress((void**)&pcur, g_cursor);
    cudaGetSymbolAddress((void**)&psrc, g_srcs);

    const int HEAD_SMEM = 2 * DD * DD * (int)sizeof(float)
                        + DD * 20 * (int)sizeof(unsigned long long);
    cudaFuncSetAttribute(chain3_mma<0>, cudaFuncAttributeMaxDynamicSharedMemorySize, CHAIN_SMEM);
    cudaFuncSetAttribute(chain3_mma<1>, cudaFuncAttributeMaxDynamicSharedMemorySize, CHAIN_SMEM);
    cudaFuncSetAttribute(head2_kernel, cudaFuncAttributeMaxDynamicSharedMemorySize, HEAD_SMEM);

    // CSR build + layer-0 gate
    cudaMemsetAsync(pcur, 0, n * sizeof(int));
    count_ext_kernel<<<(e + n + 255) / 256, 256>>>(dst, pcur, e, n);
    scan_kernel<<<1, 1024>>>(pcur, prow, n);
    const int SB = (e + n + 255) / 256;
    const int GB = (n + 7) / 8;
    scatter_gate_kernel<<<SB + GB, 256>>>(src, dst, pcur, psrc,
                                          x, Wg, bg, pg, e, n, SB);

    const int wblocks = (n * 32 + 255) / 256;
    const int PERS = 148;

    for (int i = 0; i < LL; i++) {
        const float* hin = (i == 0) ? x : ph;
        edge_agg_kernel<<<wblocks, 256>>>(prow, psrc, pg, hin, pagg, n);
        if (i < LL - 1) {
            chain3_mma<0><<<PERS, 256, CHAIN_SMEM>>>(
                pagg,
                Wt + (size_t)i * DD * DD, bt + (size_t)i * DD,
                W1 + (size_t)i * DD * DD, b1 + (size_t)i * DD,
                bng + (size_t)i * DD, bnb + (size_t)i * DD,
                bnm + (size_t)i * DD, bnv + (size_t)i * DD,
                W2 + (size_t)i * DD * DD, b2 + (size_t)i * DD,
                Wg + (size_t)(i + 1) * DD, bg + (i + 1),
                ph, pg, n);
        } else {
            chain3_mma<1><<<PERS, 256, CHAIN_SMEM>>>(
                pagg,
                Wt + (size_t)i * DD * DD, bt + (size_t)i * DD,
                W1 + (size_t)i * DD * DD, b1 + (size_t)i * DD,
                bng + (size_t)i * DD, bnb + (size_t)i * DD,
                bnm + (size_t)i * DD, bnv + (size_t)i * DD,
                W2 + (size_t)i * DD * DD, b2 + (size_t)i * DD,
                nullptr, nullptr,
                ph, nullptr, n);
        }
    }
    head2_kernel<<<(n + 127) / 128, 512, HEAD_SMEM>>>(ph, Wp1, bp1, Wp2, bp2, out, n);
}

// round 10
// speedup vs baseline: 1.6565x; 1.1276x over previous
#include <cuda_runtime.h>
#include <cuda_bf16.h>
#include <cstdint>

#define NN 50000
#define DD 128
#define EE 600000
#define CC 40
#define LL 4

// ---------------- scratch (static device globals; no allocation) ----------------
__device__ __align__(16) float g_h  [NN * DD];
__device__ __align__(16) float g_agg[NN * DD];
__device__ __align__(16) float g_gate[NN];
__device__ __align__(16) int   g_rowptr[NN + 4];
__device__ __align__(16) int   g_cursor[NN];
__device__ __align__(16) int   g_srcs[EE + NN];

// ---------------- fp32 packed-FMA helpers (head kernel) ----------------------
__device__ __forceinline__ unsigned long long ffma2(unsigned long long a,
                                                    unsigned long long b,
                                                    unsigned long long c) {
    unsigned long long d;
    asm("fma.rn.f32x2 %0, %1, %2, %3;" : "=l"(d) : "l"(a), "l"(b), "l"(c));
    return d;
}
__device__ __forceinline__ unsigned long long pack2(float x, float y) {
    unsigned long long r;
    asm("mov.b64 %0, {%1, %2};" : "=l"(r) : "f"(x), "f"(y));
    return r;
}
__device__ __forceinline__ float2 unpack2(unsigned long long v) {
    float2 f;
    asm("mov.b64 {%0, %1}, %2;" : "=f"(f.x), "=f"(f.y) : "l"(v));
    return f;
}
__device__ __forceinline__ float hsw(float x) {
    return x * fminf(fmaxf(x + 3.f, 0.f), 6.f) * (1.f / 6.f);
}
__device__ __forceinline__ uint32_t smem_u32(const void* p) {
    uint32_t a;
    asm("{ .reg .u64 t; cvta.to.shared.u64 t, %1; cvt.u32.u64 %0, t; }" : "=r"(a) : "l"(p));
    return a;
}

// split fp32 pair into bf16x2 hi (returned) and bf16x2 lo (out param).
__device__ __forceinline__ uint32_t split_pair(float x0, float x1, uint32_t& lo_pair) {
    uint32_t hi;
    asm("cvt.rn.bf16x2.f32 %0, %1, %2;" : "=r"(hi) : "f"(x1), "f"(x0));
    float h0 = __uint_as_float(hi << 16);
    float h1 = __uint_as_float(hi & 0xffff0000u);
    float l0 = x0 - h0, l1 = x1 - h1;
    asm("cvt.rn.bf16x2.f32 %0, %1, %2;" : "=r"(lo_pair) : "f"(l1), "f"(l0));
    return hi;
}

#define LDM4(r0, r1, r2, r3, addr) \
    asm volatile("ldmatrix.sync.aligned.m8n8.x4.shared.b16 {%0,%1,%2,%3}, [%4];" \
                 : "=r"(r0), "=r"(r1), "=r"(r2), "=r"(r3) : "r"(addr))

#define MMA16816(d, a0, a1, a2, a3, b0, b1) \
    asm("mma.sync.aligned.m16n8k16.row.col.f32.bf16.bf16.f32 " \
        "{%0,%1,%2,%3}, {%4,%5,%6,%7}, {%8,%9}, {%0,%1,%2,%3};" \
        : "+f"(d[0]), "+f"(d[1]), "+f"(d[2]), "+f"(d[3]) \
        : "r"(a0), "r"(a1), "r"(a2), "r"(a3), "r"(b0), "r"(b1))

// ---------------- CSR build ----------------
__global__ void count_ext_kernel(const int* __restrict__ dst, int* __restrict__ cursor,
                                 int e, int n) {
    int i = blockIdx.x * blockDim.x + threadIdx.x;
    if (i >= e + n) return;
    int d = (i < e) ? dst[i] : (i - e);
    atomicAdd(&cursor[d], 1);
}

__global__ void scan_kernel(int* __restrict__ cursor, int* __restrict__ rowptr, int n) {
    __shared__ int wsum[32];
    const int lane = threadIdx.x & 31;
    const int wid  = threadIdx.x >> 5;
    int carry = 0;
    for (int base = 0; base < n; base += 4096) {
        int idx = base + threadIdx.x * 4;
        int4 v = make_int4(0, 0, 0, 0);
        if (idx < n) v = *(const int4*)(cursor + idx);
        int t = v.x + v.y + v.z + v.w;
        int x = t;
        #pragma unroll
        for (int o = 1; o < 32; o <<= 1) {
            int y = __shfl_up_sync(0xffffffffu, x, o);
            if (lane >= o) x += y;
        }
        if (lane == 31) wsum[wid] = x;
        __syncthreads();
        if (wid == 0) {
            int s = wsum[lane];
            #pragma unroll
            for (int o = 1; o < 32; o <<= 1) {
                int y = __shfl_up_sync(0xffffffffu, s, o);
                if (lane >= o) s += y;
            }
            wsum[lane] = s;
        }
        __syncthreads();
        int excl = carry + (wid ? wsum[wid - 1] : 0) + x - t;
        if (idx < n) {
            int4 r;
            r.x = excl;
            r.y = excl + v.x;
            r.z = r.y + v.y;
            r.w = r.z + v.z;
            *(int4*)(rowptr + idx) = r;
            *(int4*)(cursor + idx) = r;
        }
        carry += wsum[31];
        __syncthreads();
    }
    if (threadIdx.x == 0) rowptr[n] = carry;
}

__global__ void __launch_bounds__(256)
scatter_kernel(const int* __restrict__ src, const int* __restrict__ dst,
               int* __restrict__ cursor, int* __restrict__ srcs, int e, int n) {
    int i = blockIdx.x * 256 + threadIdx.x;
    if (i >= e + n) return;
    int d, s;
    if (i < e) { d = dst[i]; s = src[i]; }
    else       { d = i - e;  s = i - e;  }
    int p = atomicAdd(&cursor[d], 1);
    srcs[p] = s;
}

__global__ void __launch_bounds__(256)
gate0_kernel(const float* __restrict__ x, const float* __restrict__ Wg0,
             const float* __restrict__ bg0, float* __restrict__ gate, int n) {
    int row  = blockIdx.x * 8 + (threadIdx.x >> 5);
    int lane = threadIdx.x & 31;
    if (row >= n) return;
    float4 a = ((const float4*)(x + (size_t)row * DD))[lane];
    float4 b = ((const float4*)Wg0)[lane];
    float s  = a.x * b.x + a.y * b.y + a.z * b.z + a.w * b.w;
    #pragma unroll
    for (int o = 16; o; o >>= 1) s += __shfl_xor_sync(0xffffffffu, s, o);
    if (lane == 0) gate[row] = s + bg0[0];
}

// ---------------- fused softmax-attention aggregation (warp per dst node) -----
__global__ void __launch_bounds__(256)
edge_agg_kernel(const int* __restrict__ rowptr, const int* __restrict__ srcs,
                const float* __restrict__ g, const float* __restrict__ h,
                float* __restrict__ agg, int n) {
    int gt   = blockIdx.x * blockDim.x + threadIdx.x;
    int w    = gt >> 5;
    int lane = gt & 31;
    if (w >= n) return;
    int beg = rowptr[w];
    int end = rowptr[w + 1];

    float m = -3.4e38f, s = 0.f;
    for (int j0 = beg; j0 < end; j0 += 32) {
        int  j  = j0 + lane;
        bool ok = (j < end);
        float gi = ok ? g[srcs[j]] : -3.4e38f;
        float mn = fmaxf(m, gi);
        s = s * __expf(m - mn) + (ok ? __expf(gi - mn) : 0.f);
        m = mn;
    }
    #pragma unroll
    for (int o = 16; o; o >>= 1) {
        float om = __shfl_xor_sync(0xffffffffu, m, o);
        float os = __shfl_xor_sync(0xffffffffu, s, o);
        float mn = fmaxf(m, om);
        s = s * __expf(m - mn) + os * __expf(om - mn);
        m = mn;
    }
    float inv = 1.f / s;

    float4 acc0 = make_float4(0.f, 0.f, 0.f, 0.f);
    float4 acc1 = make_float4(0.f, 0.f, 0.f, 0.f);
    for (int j0 = beg; j0 < end; j0 += 32) {
        int  j  = j0 + lane;
        bool ok = (j < end);
        int   sj  = ok ? srcs[j] : 0;
        float wgt = ok ? __expf(g[sj] - m) * inv : 0.f;
        int cnt = min(32, end - j0);
        int jj = 0;
        for (; jj + 1 < cnt; jj += 2) {
            float w0 = __shfl_sync(0xffffffffu, wgt, jj);
            float w1 = __shfl_sync(0xffffffffu, wgt, jj + 1);
            int   s0 = __shfl_sync(0xffffffffu, sj, jj);
            int   s1 = __shfl_sync(0xffffffffu, sj, jj + 1);
            float4 v0 = ((const float4*)(h + (size_t)s0 * DD))[lane];
            float4 v1 = ((const float4*)(h + (size_t)s1 * DD))[lane];
            acc0.x = fmaf(w0, v0.x, acc0.x); acc1.x = fmaf(w1, v1.x, acc1.x);
            acc0.y = fmaf(w0, v0.y, acc0.y); acc1.y = fmaf(w1, v1.y, acc1.y);
            acc0.z = fmaf(w0, v0.z, acc0.z); acc1.z = fmaf(w1, v1.z, acc1.z);
            acc0.w = fmaf(w0, v0.w, acc0.w); acc1.w = fmaf(w1, v1.w, acc1.w);
        }
        if (jj < cnt) {
            float w0 = __shfl_sync(0xffffffffu, wgt, jj);
            int   s0 = __shfl_sync(0xffffffffu, sj, jj);
            float4 v0 = ((const float4*)(h + (size_t)s0 * DD))[lane];
            acc0.x = fmaf(w0, v0.x, acc0.x);
            acc0.y = fmaf(w0, v0.y, acc0.y);
            acc0.z = fmaf(w0, v0.z, acc0.z);
            acc0.w = fmaf(w0, v0.w, acc0.w);
        }
    }
    acc0.x += acc1.x; acc0.y += acc1.y; acc0.z += acc1.z; acc0.w += acc1.w;
    ((float4*)(agg + (size_t)w * DD))[lane] = acc0;
}

// =====================================================================
// HMMA fused layer chain (persistent, 512 threads, 1 block/SM).
// 64-row tiles. Weights: 3 stages x (hi,lo) bf16 [n][k] swizzled in smem.
// 3-product split: x.w = xh.wh + xl.wh + xh.wl.
// stage0: t = A @ Wt (bt folded into b1'); stage1: z = hsw(BN(t@W1+b1'));
// stage2: h = hsw(z@W2+b2); (!LAST) gate = h . WgN + bgN
// =====================================================================
#define W_BYTES   32768
#define SM_W      0
#define SM_A      (6 * W_BYTES)        /* 196608 */
#define SM_CONST  (SM_A + 32768)       /* 229376 */
#define CHAIN_SMEM (SM_CONST + 2560)   /* 231936 */

template <int LAST>
__global__ void __launch_bounds__(512)
chain3_mma(const float* __restrict__ A,
           const float* __restrict__ Wt,  const float* __restrict__ bt,
           const float* __restrict__ W1,  const float* __restrict__ b1,
           const float* __restrict__ bng, const float* __restrict__ bnb,
           const float* __restrict__ bnm, const float* __restrict__ bnv,
           const float* __restrict__ W2,  const float* __restrict__ b2,
           const float* __restrict__ WgN, const float* __restrict__ bgN,
           float* __restrict__ hout, float* __restrict__ gate, int nrows) {
    extern __shared__ char smem[];
    const uint32_t sb = smem_u32(smem);
    float* cst = (float*)(smem + SM_CONST);   // b1' | scale | shift | b2 | wg
    float* gpp = (float*)(smem + SM_A);       // gate partials (reuses dead A region)
    const int tid  = threadIdx.x;
    const int wid  = tid >> 5;
    const int lane = tid & 31;
    const int mt = wid & 3;          // row block of 16 (64 rows total)
    const int nb = wid >> 2;         // col block of 32
    const int g  = lane >> 2, tg = lane & 3;
    const int lq = lane >> 3, lr = lane & 7;

    // ---- stage weights: fp32 -> (hi,lo) bf16, transpose to [n][k], swizzle ----
    const float* WS[3] = {Wt, W1, W2};
    #pragma unroll
    for (int m = 0; m < 3; m++) {
        char* hi_s = smem + SM_W + m * 2 * W_BYTES;
        char* lo_s = hi_s + W_BYTES;
        const float* W = WS[m];
        for (int i = tid; i < DD * DD; i += 512) {
            int k = i >> 7, n = i & 127;
            float w = W[i];
            __nv_bfloat16 hb = __float2bfloat16(w);
            __nv_bfloat16 lb = __float2bfloat16(w - __bfloat162float(hb));
            int off = n * 256 + (((k >> 3) ^ (n & 7)) << 4) + (k & 7) * 2;
            *(__nv_bfloat16*)(hi_s + off) = hb;
            *(__nv_bfloat16*)(lo_s + off) = lb;
        }
    }
    // ---- epilogue constants; fold bt: b1' = bt @ W1 + b1 ----
    if (tid < 128) {
        float a = b1[tid];
        for (int k = 0; k < 128; k++) a = fmaf(bt[k], W1[k * 128 + tid], a);
        cst[tid] = a;
        float sv = bng[tid] * rsqrtf(bnv[tid] + 1e-5f);
        cst[128 + tid] = sv;
        cst[256 + tid] = bnb[tid] - bnm[tid] * sv;
        cst[384 + tid] = b2[tid];
        cst[512 + tid] = LAST ? 0.f : WgN[tid];
    }
    const float bgv = LAST ? 0.f : bgN[0];

    const uint32_t As_hi = sb + SM_A;
    const uint32_t As_lo = As_hi + 16384;     // 64 rows * 256B per plane
    const int a_row = mt * 16 + lr + ((lq & 1) << 3);
    const int a_kh  = lq >> 1;
    const int b_row = nb * 32 + lr + ((lq >> 1) << 3);
    const int b_kh  = lq & 1;
    const uint32_t aRowHi = As_hi + a_row * 256;
    const uint32_t aRowLo = As_lo + a_row * 256;
    const int r0l = mt * 16 + g;              // epilogue rows r0l, r0l+8

    const int ntiles = (nrows + 63) >> 6;
    int t = blockIdx.x;
    if (t < ntiles) {   // initial A tile load+split+store
        #pragma unroll
        for (int it = 0; it < 4; it++) {
            int s2 = it * 512 + tid;
            int r = s2 >> 5, c4 = s2 & 31;
            int grow = t * 64 + r;
            float4 f = make_float4(0.f, 0.f, 0.f, 0.f);
            if (grow < nrows) f = ((const float4*)(A + (size_t)grow * DD))[c4];
            uint32_t l01, l23;
            uint32_t h01 = split_pair(f.x, f.y, l01);
            uint32_t h23 = split_pair(f.z, f.w, l23);
            uint32_t off = (uint32_t)r * 256
                         + ((uint32_t)((c4 >> 1) ^ (r & 7)) << 4) + (c4 & 1) * 8;
            *(uint2*)(smem + SM_A + off)         = make_uint2(h01, h23);
            *(uint2*)(smem + SM_A + 16384 + off) = make_uint2(l01, l23);
        }
    }

    for (; t < ntiles; t += gridDim.x) {
        __syncthreads();   // As tile ready (and weights on first pass)

        const int tn = t + gridDim.x;
        float4 pf[4];

        #pragma unroll
        for (int st = 0; st < 3; st++) {
            const uint32_t wHi = sb + SM_W + st * 2 * W_BYTES;
            const uint32_t wLo = wHi + W_BYTES;
            const uint32_t bRowHi = wHi + b_row * 256;
            const uint32_t bRowLo = wLo + b_row * 256;

            if (st == 2 && tn < ntiles) {  // prefetch next tile (overlaps stage2)
                #pragma unroll
                for (int it = 0; it < 4; it++) {
                    int s2 = it * 512 + tid;
                    int r = s2 >> 5, c4 = s2 & 31;
                    int grow = tn * 64 + r;
                    pf[it] = (grow < nrows) ? ((const float4*)(A + (size_t)grow * DD))[c4]
                                            : make_float4(0.f, 0.f, 0.f, 0.f);
                }
            }

            float acc[4][4];
            #pragma unroll
            for (int i = 0; i < 4; i++) {
                acc[i][0] = 0.f; acc[i][1] = 0.f; acc[i][2] = 0.f; acc[i][3] = 0.f;
            }
            #pragma unroll
            for (int kk = 0; kk < 8; kk++) {
                uint32_t ca = (uint32_t)(((2 * kk + a_kh) ^ lr) << 4);
                uint32_t cb = (uint32_t)(((2 * kk + b_kh) ^ lr) << 4);
                uint32_t ah0, ah1, ah2, ah3, al0, al1, al2, al3;
                LDM4(ah0, ah1, ah2, ah3, aRowHi + ca);
                LDM4(al0, al1, al2, al3, aRowLo + ca);
                uint32_t bh0, bh1, bh2, bh3, bh4, bh5, bh6, bh7;
                LDM4(bh0, bh1, bh2, bh3, bRowHi + cb);
                LDM4(bh4, bh5, bh6, bh7, bRowHi + 4096 + cb);
                uint32_t bl0, bl1, bl2, bl3, bl4, bl5, bl6, bl7;
                LDM4(bl0, bl1, bl2, bl3, bRowLo + cb);
                LDM4(bl4, bl5, bl6, bl7, bRowLo + 4096 + cb);
                MMA16816(acc[0], ah0, ah1, ah2, ah3, bh0, bh1);
                MMA16816(acc[1], ah0, ah1, ah2, ah3, bh2, bh3);
                MMA16816(acc[2], ah0, ah1, ah2, ah3, bh4, bh5);
                MMA16816(acc[3], ah0, ah1, ah2, ah3, bh6, bh7);
                MMA16816(acc[0], al0, al1, al2, al3, bh0, bh1);
                MMA16816(acc[1], al0, al1, al2, al3, bh2, bh3);
                MMA16816(acc[2], al0, al1, al2, al3, bh4, bh5);
                MMA16816(acc[3], al0, al1, al2, al3, bh6, bh7);
                MMA16816(acc[0], ah0, ah1, ah2, ah3, bl0, bl1);
                MMA16816(acc[1], ah0, ah1, ah2, ah3, bl2, bl3);
                MMA16816(acc[2], ah0, ah1, ah2, ah3, bl4, bl5);
                MMA16816(acc[3], ah0, ah1, ah2, ah3, bl6, bl7);
            }
            __syncthreads();   // all warps done reading As before overwrite

            if (st < 2) {
                #pragma unroll
                for (int tt = 0; tt < 4; tt++) {
                    int ct = nb * 32 + tt * 8;
                    int c0 = ct + 2 * tg, c1 = c0 + 1;
                    float v0 = acc[tt][0], v1 = acc[tt][1];
                    float v2 = acc[tt][2], v3 = acc[tt][3];
                    if (st == 1) {
                        v0 = hsw((v0 + cst[c0]) * cst[128 + c0] + cst[256 + c0]);
                        v1 = hsw((v1 + cst[c1]) * cst[128 + c1] + cst[256 + c1]);
                        v2 = hsw((v2 + cst[c0]) * cst[128 + c0] + cst[256 + c0]);
                        v3 = hsw((v3 + cst[c1]) * cst[128 + c1] + cst[256 + c1]);
                    }
                    uint32_t lo01, lo23;
                    uint32_t h01 = split_pair(v0, v1, lo01);
                    uint32_t h23 = split_pair(v2, v3, lo23);
                    uint32_t chunk = (uint32_t)(((ct >> 3) ^ (r0l & 7)) << 4) + 4 * tg;
                    uint32_t off0 = (uint32_t)r0l * 256 + chunk;
                    uint32_t off1 = (uint32_t)(r0l + 8) * 256 + chunk;
                    *(uint32_t*)(smem + SM_A + off0)         = h01;
                    *(uint32_t*)(smem + SM_A + off1)         = h23;
                    *(uint32_t*)(smem + SM_A + 16384 + off0) = lo01;
                    *(uint32_t*)(smem + SM_A + 16384 + off1) = lo23;
                }
                __syncthreads();
            } else {
                int gr0 = t * 64 + r0l, gr1 = gr0 + 8;
                float p0 = 0.f, p1 = 0.f;
                #pragma unroll
                for (int tt = 0; tt < 4; tt++) {
                    int ct = nb * 32 + tt * 8;
                    int c0 = ct + 2 * tg, c1 = c0 + 1;
                    float q0 = hsw(acc[tt][0] + cst[384 + c0]);
                    float q1 = hsw(acc[tt][1] + cst[384 + c1]);
                    float q2 = hsw(acc[tt][2] + cst[384 + c0]);
                    float q3 = hsw(acc[tt][3] + cst[384 + c1]);
                    if (!LAST) {
                        p0 = fmaf(q0, cst[512 + c0], fmaf(q1, cst[512 + c1], p0));
                        p1 = fmaf(q2, cst[512 + c0], fmaf(q3, cst[512 + c1], p1));
                    }
                    if (gr0 < nrows)
                        *(float2*)(hout + (size_t)gr0 * DD + c0) = make_float2(q0, q1);
                    if (gr1 < nrows)
                        *(float2*)(hout + (size_t)gr1 * DD + c0) = make_float2(q2, q3);
                }
                if (!LAST) {
                    p0 += __shfl_xor_sync(0xffffffffu, p0, 1);
                    p0 += __shfl_xor_sync(0xffffffffu, p0, 2);
                    p1 += __shfl_xor_sync(0xffffffffu, p1, 1);
                    p1 += __shfl_xor_sync(0xffffffffu, p1, 2);
                    if (tg == 0) {  // gate partials into dead As region
                        gpp[r0l * 4 + nb]       = p0;
                        gpp[(r0l + 8) * 4 + nb] = p1;
                    }
                }
            }
        }
        if (!LAST) {
            __syncthreads();
            if (tid < 64) {
                int gr = t * 64 + tid;
                if (gr < nrows)
                    gate[gr] = gpp[tid * 4] + gpp[tid * 4 + 1]
                             + gpp[tid * 4 + 2] + gpp[tid * 4 + 3] + bgv;
            }
            __syncthreads();
        }
        // store prefetched tile (split) into As; loop-top sync publishes it
        if (tn < ntiles) {
            #pragma unroll
            for (int it = 0; it < 4; it++) {
                int s2 = it * 512 + tid;
                int r = s2 >> 5, c4 = s2 & 31;
                float4 f = pf[it];
                uint32_t l01, l23;
                uint32_t h01 = split_pair(f.x, f.y, l01);
                uint32_t h23 = split_pair(f.z, f.w, l23);
                uint32_t off = (uint32_t)r * 256
                             + ((uint32_t)((c4 >> 1) ^ (r & 7)) << 4) + (c4 & 1) * 8;
                *(uint2*)(smem + SM_A + off)         = make_uint2(h01, h23);
                *(uint2*)(smem + SM_A + 16384 + off) = make_uint2(l01, l23);
            }
        }
    }
}

// ---------------- FFMA tile MMA for head ----------------
template <int R>
__device__ __forceinline__ void mm_stage(const float* __restrict__ As,
                                         const float* __restrict__ Ws,
                                         unsigned long long acc[R][2],
                                         int tr, int tc) {
    #pragma unroll
    for (int i = 0; i < R; i++) { acc[i][0] = 0ull; acc[i][1] = 0ull; }
    const float4*     Arow = (const float4*)(As + tr * R * DD);
    const ulonglong2* Wsu  = ((const ulonglong2*)Ws) + tc;
    #pragma unroll 2
    for (int k4 = 0; k4 < 32; k4++) {
        float4 a[R];
        #pragma unroll
        for (int i = 0; i < R; i++) a[i] = Arow[i * 32 + k4];
        #pragma unroll
        for (int kk = 0; kk < 4; kk++) {
            ulonglong2 wp = Wsu[(k4 * 4 + kk) * 32];
            #pragma unroll
            for (int i = 0; i < R; i++) {
                float av = (kk == 0) ? a[i].x : (kk == 1) ? a[i].y : (kk == 2) ? a[i].z : a[i].w;
                unsigned long long ad = pack2(av, av);
                acc[i][0] = ffma2(ad, wp.x, acc[i][0]);
                acc[i][1] = ffma2(ad, wp.y, acc[i][1]);
            }
        }
    }
}

// ---------------- head: z = hsw(h@Wp1+bp1); logits=z@Wp2+bp2; log_softmax ----
__global__ void __launch_bounds__(512)
head2_kernel(const float* __restrict__ h, const float* __restrict__ Wp1,
             const float* __restrict__ bp1, const float* __restrict__ Wp2,
             const float* __restrict__ bp2, float* __restrict__ out, int n) {
    extern __shared__ float sm[];
    float* Wp1s = sm;
    float* As   = sm + 16384;
    unsigned long long* wsh = (unsigned long long*)(sm + 32768);
    const int tid = threadIdx.x;
    const int tc  = tid & 31;
    const int tr  = tid >> 5;
    const int r0  = blockIdx.x * 128;

    {
        const float4* w = (const float4*)Wp1;
        float4* s = (float4*)Wp1s;
        #pragma unroll
        for (int it = 0; it < 8; it++) s[it * 512 + tid] = w[it * 512 + tid];
    }
    for (int idx = tid; idx < DD * 20; idx += 512) {
        int k = idx / 20, j = idx % 20;
        wsh[idx] = pack2(Wp2[k * CC + 2 * j], Wp2[k * CC + 2 * j + 1]);
    }
    {
        float4* As4 = (float4*)As;
        #pragma unroll
        for (int it = 0; it < 8; it++) {
            int idx = it * 512 + tid;
            int r = idx >> 5, c4 = idx & 31;
            float4 v = make_float4(0.f, 0.f, 0.f, 0.f);
            if (r0 + r < n) v = ((const float4*)(h + (size_t)(r0 + r) * DD))[c4];
            As4[idx] = v;
        }
    }
    __syncthreads();

    unsigned long long acc1[8][2];
    mm_stage<8>(As, Wp1s, acc1, tr, tc);
    const int c0 = tc * 4;
    float bc[4];
    #pragma unroll
    for (int j = 0; j < 4; j++) bc[j] = bp1[c0 + j];
    float zz[8][4];
    #pragma unroll
    for (int i = 0; i < 8; i++) {
        float2 v0 = unpack2(acc1[i][0]), v1 = unpack2(acc1[i][1]);
        float vv[4] = {v0.x, v0.y, v1.x, v1.y};
        #pragma unroll
        for (int j = 0; j < 4; j++) zz[i][j] = hsw(vv[j] + bc[j]);
    }
    __syncthreads();
    #pragma unroll
    for (int i = 0; i < 8; i++)
        ((float4*)(As + (tr * 8 + i) * DD))[tc] = make_float4(zz[i][0], zz[i][1], zz[i][2], zz[i][3]);
    __syncthreads();

    const int rl = tid >> 2;
    const int q  = tid & 3;
    unsigned long long acc[5];
    #pragma unroll
    for (int j = 0; j < 5; j++)
        acc[j] = pack2(bp2[q * 10 + 2 * j], bp2[q * 10 + 2 * j + 1]);
    const float* ar = As + rl * DD;
    #pragma unroll 4
    for (int k = 0; k < DD; k++) {
        float a = ar[k];
        unsigned long long ad = pack2(a, a);
        const unsigned long long* wr = wsh + k * 20 + q * 5;
        #pragma unroll
        for (int j = 0; j < 5; j++) acc[j] = ffma2(ad, wr[j], acc[j]);
    }
    float vals[10];
    #pragma unroll
    for (int j = 0; j < 5; j++) {
        float2 p = unpack2(acc[j]);
        vals[2 * j] = p.x;
        vals[2 * j + 1] = p.y;
    }
    float mx = vals[0];
    #pragma unroll
    for (int c = 1; c < 10; c++) mx = fmaxf(mx, vals[c]);
    mx = fmaxf(mx, __shfl_xor_sync(0xffffffffu, mx, 1));
    mx = fmaxf(mx, __shfl_xor_sync(0xffffffffu, mx, 2));
    float s = 0.f;
    #pragma unroll
    for (int c = 0; c < 10; c++) s += __expf(vals[c] - mx);
    s += __shfl_xor_sync(0xffffffffu, s, 1);
    s += __shfl_xor_sync(0xffffffffu, s, 2);
    float lse = mx + logf(s);
    int gr = r0 + rl;
    if (gr < n) {
        #pragma unroll
        for (int c = 0; c < 10; c++) out[(size_t)gr * CC + q * 10 + c] = vals[c] - lse;
    }
}

// ---------------- launch orchestration ----------------
extern "C" void kernel_launch(void* const* d_in, const int* in_sizes, int n_in,
                              void* d_out, int out_size) {
    const float* x   = (const float*)d_in[0];
    const int*   src = (const int*)d_in[1];
    const int*   dst = (const int*)d_in[2];
    const float* Wg  = (const float*)d_in[3];
    const float* bg  = (const float*)d_in[4];
    const float* Wt  = (const float*)d_in[5];
    const float* bt  = (const float*)d_in[6];
    const float* W1  = (const float*)d_in[7];
    const float* b1  = (const float*)d_in[8];
    const float* bng = (const float*)d_in[9];
    const float* bnb = (const float*)d_in[10];
    const float* bnm = (const float*)d_in[11];
    const float* bnv = (const float*)d_in[12];
    const float* W2  = (const float*)d_in[13];
    const float* b2  = (const float*)d_in[14];
    const float* Wp1 = (const float*)d_in[15];
    const float* bp1 = (const float*)d_in[16];
    const float* Wp2 = (const float*)d_in[17];
    const float* bp2 = (const float*)d_in[18];
    float* out = (float*)d_out;

    const int n = in_sizes[0] / DD;
    const int e = in_sizes[1];

    float *ph, *pagg, *pg;
    int *prow, *pcur, *psrc;
    cudaGetSymbolAddress((void**)&ph,   g_h);
    cudaGetSymbolAddress((void**)&pagg, g_agg);
    cudaGetSymbolAddress((void**)&pg,   g_gate);
    cudaGetSymbolAddress((void**)&prow, g_rowptr);
    cudaGetSymbolAddress((void**)&pcur, g_cursor);
    cudaGetSymbolAddress((void**)&psrc, g_srcs);

    const int HEAD_SMEM = 2 * DD * DD * (int)sizeof(float)
                        + DD * 20 * (int)sizeof(unsigned long long);
    cudaFuncSetAttribute(chain3_mma<0>, cudaFuncAttributeMaxDynamicSharedMemorySize, CHAIN_SMEM);
    cudaFuncSetAttribute(chain3_mma<1>, cudaFuncAttributeMaxDynamicSharedMemorySize, CHAIN_SMEM);
    cudaFuncSetAttribute(head2_kernel, cudaFuncAttributeMaxDynamicSharedMemorySize, HEAD_SMEM);

    // CSR build + layer-0 gate (kernel launch indices: 0..3)
    cudaMemsetAsync(pcur, 0, n * sizeof(int));
    count_ext_kernel<<<(e + n + 255) / 256, 256>>>(dst, pcur, e, n);       // 0
    scan_kernel<<<1, 1024>>>(pcur, prow, n);                               // 1
    scatter_kernel<<<(e + n + 255) / 256, 256>>>(src, dst, pcur, psrc, e, n); // 2
    gate0_kernel<<<(n + 7) / 8, 256>>>(x, Wg, bg, pg, n);                  // 3

    const int wblocks = (n * 32 + 255) / 256;
    const int PERS = 148;

    for (int i = 0; i < LL; i++) {
        const float* hin = (i == 0) ? x : ph;
        edge_agg_kernel<<<wblocks, 256>>>(prow, psrc, pg, hin, pagg, n);   // 4 (layer0)
        if (i < LL - 1) {
            chain3_mma<0><<<PERS, 512, CHAIN_SMEM>>>(                      // 5 (layer0)
                pagg,
                Wt + (size_t)i * DD * DD, bt + (size_t)i * DD,
                W1 + (size_t)i * DD * DD, b1 + (size_t)i * DD,
                bng + (size_t)i * DD, bnb + (size_t)i * DD,
                bnm + (size_t)i * DD, bnv + (size_t)i * DD,
                W2 + (size_t)i * DD * DD, b2 + (size_t)i * DD,
                Wg + (size_t)(i + 1) * DD, bg + (i + 1),
                ph, pg, n);
        } else {
            chain3_mma<1><<<PERS, 512, CHAIN_SMEM>>>(
                pagg,
                Wt + (size_t)i * DD * DD, bt + (size_t)i * DD,
                W1 + (size_t)i * DD * DD, b1 + (size_t)i * DD,
                bng + (size_t)i * DD, bnb + (size_t)i * DD,
                bnm + (size_t)i * DD, bnv + (size_t)i * DD,
                W2 + (size_t)i * DD * DD, b2 + (size_t)i * DD,
                nullptr, nullptr,
                ph, nullptr, n);
        }
    }
    head2_kernel<<<(n + 127) / 128, 512, HEAD_SMEM>>>(ph, Wp1, bp1, Wp2, bp2, out, n);
}